// round 1
// baseline (speedup 1.0000x reference)
#include <cuda_runtime.h>
#include <cuda_bf16.h>
#include <math.h>

// Problem constants (fixed by the dataset instance)
#define NHEADS 8
#define NPOINTS 4
#define DMODEL 256
#define DHEAD 32
#define BATCH 8
#define QLEN 2048
#define HWTOT 10000

// Scratch (device globals — no allocation allowed)
__device__ float g_values[(size_t)BATCH * HWTOT * DMODEL];   // 81.92 MB
__device__ float g_sampled[(size_t)BATCH * QLEN * DMODEL];   // 16.78 MB

// ---------------------------------------------------------------------------
// SGEMM: C[M,N] = A[M,K] @ B[K,N] + bias[N]   (all row-major, fp32)
// Tile 128x128x8, 256 threads, 8x8 microtile per thread.
// ---------------------------------------------------------------------------
#define BM 128
#define BN 128
#define BK 8
#define TM 8
#define TN 8

__global__ __launch_bounds__(256) void sgemm_bias_kernel(
    const float* __restrict__ A, const float* __restrict__ B,
    const float* __restrict__ bias, float* __restrict__ C,
    int M, int N, int K)
{
    __shared__ float As[BK][BM];
    __shared__ float Bs[BK][BN];

    const int bx = blockIdx.x;  // along N
    const int by = blockIdx.y;  // along M
    const int tid = threadIdx.x;

    const int trow = tid / (BN / TN);  // 0..15
    const int tcol = tid % (BN / TN);  // 0..15

    // loader mapping: one float4 per thread per tile
    const int a_r = tid >> 1;          // 0..127
    const int a_c = (tid & 1) * 4;     // 0 or 4
    const int b_r = tid >> 5;          // 0..7
    const int b_c = (tid & 31) * 4;    // 0..124

    const long a_row = (long)by * BM + a_r;
    const float* Abase = A + a_row * K;
    const float* Bbase = B + (long)bx * BN;

    float acc[TM][TN];
    #pragma unroll
    for (int i = 0; i < TM; i++)
        #pragma unroll
        for (int j = 0; j < TN; j++) acc[i][j] = 0.f;

    for (int k0 = 0; k0 < K; k0 += BK) {
        // load A tile (transposed into As)
        float4 av = make_float4(0.f, 0.f, 0.f, 0.f);
        if (a_row < M) av = *(const float4*)(Abase + k0 + a_c);
        As[a_c + 0][a_r] = av.x;
        As[a_c + 1][a_r] = av.y;
        As[a_c + 2][a_r] = av.z;
        As[a_c + 3][a_r] = av.w;
        // load B tile
        float4 bv = *(const float4*)(Bbase + (long)(k0 + b_r) * N + b_c);
        *(float4*)&Bs[b_r][b_c] = bv;
        __syncthreads();

        #pragma unroll
        for (int k = 0; k < BK; k++) {
            float ra[TM], rb[TN];
            *(float4*)&ra[0] = *(const float4*)&As[k][trow * TM + 0];
            *(float4*)&ra[4] = *(const float4*)&As[k][trow * TM + 4];
            *(float4*)&rb[0] = *(const float4*)&Bs[k][tcol * TN + 0];
            *(float4*)&rb[4] = *(const float4*)&Bs[k][tcol * TN + 4];
            #pragma unroll
            for (int i = 0; i < TM; i++)
                #pragma unroll
                for (int j = 0; j < TN; j++)
                    acc[i][j] = fmaf(ra[i], rb[j], acc[i][j]);
        }
        __syncthreads();
    }

    // epilogue: add bias, write
    #pragma unroll
    for (int i = 0; i < TM; i++) {
        long r = (long)by * BM + trow * TM + i;
        if (r >= M) continue;
        #pragma unroll
        for (int j = 0; j < TN; j += 4) {
            int c = bx * BN + tcol * TN + j;
            float4 v;
            v.x = acc[i][j + 0] + bias[c + 0];
            v.y = acc[i][j + 1] + bias[c + 1];
            v.z = acc[i][j + 2] + bias[c + 2];
            v.w = acc[i][j + 3] + bias[c + 3];
            *(float4*)(C + r * N + c) = v;
        }
    }
}

// ---------------------------------------------------------------------------
// Fused: offset/attn projection + softmax + bilinear sampling.
// One block per (b,q), 256 threads.
// ---------------------------------------------------------------------------
__global__ __launch_bounds__(256) void deform_sample_kernel(
    const float* __restrict__ query,
    const float* __restrict__ ref_pts,
    const float* __restrict__ W_off, const float* __restrict__ b_off,
    const float* __restrict__ W_attn, const float* __restrict__ b_attn,
    const int* __restrict__ hp, const int* __restrict__ wp,
    float* __restrict__ sampled)
{
    const int bq = blockIdx.x;           // 0 .. B*Q-1
    const int tid = threadIdx.x;         // 256

    __shared__ float q_sm[DMODEL];
    __shared__ float off_sm[NHEADS * NPOINTS * 2];   // 64
    __shared__ float attn_sm[NHEADS * NPOINTS];      // 32
    __shared__ int   cx0[NHEADS * NPOINTS];
    __shared__ int   cy0[NHEADS * NPOINTS];
    __shared__ int   cx1[NHEADS * NPOINTS];
    __shared__ int   cy1[NHEADS * NPOINTS];
    __shared__ float cw00[NHEADS * NPOINTS];
    __shared__ float cw01[NHEADS * NPOINTS];
    __shared__ float cw10[NHEADS * NPOINTS];
    __shared__ float cw11[NHEADS * NPOINTS];

    q_sm[tid] = query[(long)bq * DMODEL + tid];
    __syncthreads();

    // ---- projections (96 outputs: 64 offsets, 32 attn logits)
    if (tid < 96) {
        float acc;
        if (tid < 64) {
            acc = b_off[tid];
            #pragma unroll 8
            for (int k = 0; k < DMODEL; k++)
                acc = fmaf(q_sm[k], W_off[k * 64 + tid], acc);
            off_sm[tid] = acc;
        } else {
            int n = tid - 64;
            acc = b_attn[n];
            #pragma unroll 8
            for (int k = 0; k < DMODEL; k++)
                acc = fmaf(q_sm[k], W_attn[k * 32 + n], acc);
            attn_sm[n] = acc;
        }
    }
    __syncthreads();

    // ---- softmax over P, one thread per head
    if (tid < NHEADS) {
        float m = -1e30f;
        #pragma unroll
        for (int p = 0; p < NPOINTS; p++) m = fmaxf(m, attn_sm[tid * NPOINTS + p]);
        float e[NPOINTS], s = 0.f;
        #pragma unroll
        for (int p = 0; p < NPOINTS; p++) {
            e[p] = expf(attn_sm[tid * NPOINTS + p] - m);
            s += e[p];
        }
        float inv = 1.f / s;
        #pragma unroll
        for (int p = 0; p < NPOINTS; p++) attn_sm[tid * NPOINTS + p] = e[p] * inv;
    }

    // ---- bilinear setup, one thread per (h,p)
    if (tid < NHEADS * NPOINTS) {
        const int ww = *wp;
        const int hh = *hp;
        float rx = ref_pts[(long)bq * 2 + 0];
        float ry = ref_pts[(long)bq * 2 + 1];
        float lx = fminf(fmaxf(rx + off_sm[tid * 2 + 0], 0.f), 1.f);
        float ly = fminf(fmaxf(ry + off_sm[tid * 2 + 1], 0.f), 1.f);
        float sx = lx * (float)(ww - 1);
        float sy = ly * (float)(hh - 1);
        int x0 = (int)floorf(sx); x0 = min(max(x0, 0), ww - 1);
        int y0 = (int)floorf(sy); y0 = min(max(y0, 0), hh - 1);
        int x1 = min(x0 + 1, ww - 1);
        int y1 = min(y0 + 1, hh - 1);
        float wx1 = sx - (float)x0, wx0 = 1.f - wx1;
        float wy1 = sy - (float)y0, wy0 = 1.f - wy1;
        cx0[tid] = x0; cy0[tid] = y0; cx1[tid] = x1; cy1[tid] = y1;
        cw00[tid] = wx0 * wy0;   // (x0,y0)
        cw01[tid] = wx0 * wy1;   // (x0,y1)
        cw10[tid] = wx1 * wy0;   // (x1,y0)
        cw11[tid] = wx1 * wy1;   // (x1,y1)
    }
    __syncthreads();

    // ---- accumulate: thread = (head, channel). warp == one head -> 128B lines
    const int head = tid >> 5;
    const int ch = tid & 31;
    const int b = bq / QLEN;
    const int ww = *wp;
    const float* vb = g_values + (long)b * HWTOT * DMODEL + head * DHEAD + ch;

    float acc = 0.f;
    #pragma unroll
    for (int p = 0; p < NPOINTS; p++) {
        int idx = head * NPOINTS + p;
        int x0 = cx0[idx], y0 = cy0[idx], x1 = cx1[idx], y1 = cy1[idx];
        float g00 = vb[(long)(y0 * ww + x0) * DMODEL];
        float g01 = vb[(long)(y1 * ww + x0) * DMODEL];
        float g10 = vb[(long)(y0 * ww + x1) * DMODEL];
        float g11 = vb[(long)(y1 * ww + x1) * DMODEL];
        float bl = g00 * cw00[idx] + g01 * cw01[idx] + g10 * cw10[idx] + g11 * cw11[idx];
        acc = fmaf(bl, attn_sm[idx], acc);
    }
    sampled[(long)bq * DMODEL + tid] = acc;
}

// ---------------------------------------------------------------------------
// Launch
// ---------------------------------------------------------------------------
extern "C" void kernel_launch(void* const* d_in, const int* in_sizes, int n_in,
                              void* d_out, int out_size)
{
    const float* query   = (const float*)d_in[0];
    const float* ref_pts = (const float*)d_in[1];
    const float* inp     = (const float*)d_in[2];
    const int*   hp      = (const int*)d_in[3];
    const int*   wp      = (const int*)d_in[4];
    const float* W_off   = (const float*)d_in[5];
    const float* b_off   = (const float*)d_in[6];
    const float* W_attn  = (const float*)d_in[7];
    const float* b_attn  = (const float*)d_in[8];
    const float* W_val   = (const float*)d_in[9];
    const float* b_val   = (const float*)d_in[10];
    const float* W_out   = (const float*)d_in[11];
    const float* b_out   = (const float*)d_in[12];
    float* out = (float*)d_out;

    float* values_ptr = nullptr;
    float* sampled_ptr = nullptr;
    cudaGetSymbolAddress((void**)&values_ptr, g_values);
    cudaGetSymbolAddress((void**)&sampled_ptr, g_sampled);

    const int M1 = BATCH * HWTOT;   // 80000
    const int M3 = BATCH * QLEN;    // 16384
    const int N = DMODEL, K = DMODEL;

    // 1) values = input_flatten @ W_val + b_val
    {
        dim3 grid(N / BN, (M1 + BM - 1) / BM);
        sgemm_bias_kernel<<<grid, 256>>>(inp, W_val, b_val, values_ptr, M1, N, K);
    }

    // 2) fused offsets/attn/softmax/bilinear sampling
    {
        deform_sample_kernel<<<BATCH * QLEN, 256>>>(
            query, ref_pts, W_off, b_off, W_attn, b_attn, hp, wp, sampled_ptr);
    }

    // 3) out = sampled @ W_out + b_out
    {
        dim3 grid(N / BN, (M3 + BM - 1) / BM);
        sgemm_bias_kernel<<<grid, 256>>>(sampled_ptr, W_out, b_out, out, M3, N, K);
    }
}

// round 2
// speedup vs baseline: 2.0178x; 2.0178x over previous
#include <cuda_runtime.h>
#include <cuda_bf16.h>
#include <math.h>
#include <stdint.h>

// Problem constants (fixed by the dataset instance)
#define NHEADS 8
#define NPOINTS 4
#define DMODEL 256
#define DHEAD 32
#define BATCH 8
#define QLEN 2048
#define HWTOT 10000
#define NPROJ 96   // 64 offset cols + 32 attn cols

// Scratch (device globals — no allocation allowed)
__device__ float g_values[(size_t)BATCH * HWTOT * DMODEL];   // 81.92 MB
__device__ float g_sampled[(size_t)BATCH * QLEN * DMODEL];   // 16.78 MB
__device__ float g_proj[(size_t)BATCH * QLEN * NPROJ];       //  6.29 MB
__device__ float g_Wcat[DMODEL * NPROJ];
__device__ float g_bcat[NPROJ];

// ---------------------------------------------------------------------------
// helpers
// ---------------------------------------------------------------------------
__device__ __forceinline__ uint32_t f2tf32(float x) {
    uint32_t u;
    asm("cvt.rna.tf32.f32 %0, %1;" : "=r"(u) : "f"(x));
    return u;
}
__device__ __forceinline__ float tf32f(float x) {
    return __uint_as_float(f2tf32(x));
}

__device__ __forceinline__ void mma8(float d[4],
                                     uint32_t a0, uint32_t a1, uint32_t a2, uint32_t a3,
                                     uint32_t b0, uint32_t b1) {
    asm volatile(
        "mma.sync.aligned.m16n8k8.row.col.f32.tf32.tf32.f32 "
        "{%0,%1,%2,%3}, {%4,%5,%6,%7}, {%8,%9}, {%0,%1,%2,%3};"
        : "+f"(d[0]), "+f"(d[1]), "+f"(d[2]), "+f"(d[3])
        : "r"(a0), "r"(a1), "r"(a2), "r"(a3), "r"(b0), "r"(b1));
}

// ---------------------------------------------------------------------------
// TF32 tensor-core GEMM: C[M,N] = A[M,K] @ B[K,N] + bias[N], row-major fp32.
// Block tile 128x128x16, 256 threads (8 warps as 4x2), warp tile 32x64.
// SPLIT=true -> 3xTF32 (hi/lo) for fp32-level accuracy.
// Requires K % 16 == 0, N % 4 == 0.
// ---------------------------------------------------------------------------
#define GBM 128
#define GBN 128
#define GBK 16
#define AS_STRIDE 20    // [m][k] padded: bank-conflict-free fragment reads
#define BS_STRIDE 132   // [k][n] padded

template<bool SPLIT>
__global__ __launch_bounds__(256) void tf32_gemm_kernel(
    const float* __restrict__ A, const float* __restrict__ B,
    const float* __restrict__ bias, float* __restrict__ C,
    int M, int N, int K)
{
    __shared__ __align__(16) float As[2][GBM][AS_STRIDE];
    __shared__ __align__(16) float Bs[2][GBK][BS_STRIDE];

    const int t = threadIdx.x;
    const int warp = t >> 5;
    const int lane = t & 31;
    const int g = lane >> 2;    // group id (0..7)
    const int tig = lane & 3;   // thread-in-group (0..3)
    const int wm = (warp >> 1) * 32;  // warp m offset in tile
    const int wn = (warp & 1) * 64;   // warp n offset in tile

    const int rowTile = blockIdx.y * GBM;
    const int colTile = blockIdx.x * GBN;

    // loader mapping: A tile = 128x16 = 512 float4; B tile = 16x128 = 512 float4
    const int ar0 = t >> 2;            // rows 0..63
    const int ar1 = ar0 + 64;          // rows 64..127
    const int ac = (t & 3) * 4;        // k-offset within tile {0,4,8,12}
    const int bk0 = t >> 5;            // k rows 0..7
    const int bk1 = bk0 + 8;           // k rows 8..15
    const int bc = (t & 31) * 4;       // n-offset within tile {0..124}

    const bool aok0 = (rowTile + ar0) < M;
    const bool aok1 = (rowTile + ar1) < M;
    const bool bok = (colTile + bc) < N;   // N%4==0 so whole float4 in/out

    const float* Ap0 = A + (long)(rowTile + ar0) * K + ac;
    const float* Ap1 = A + (long)(rowTile + ar1) * K + ac;
    const float* Bp0 = B + (long)bk0 * N + colTile + bc;
    const float* Bp1 = B + (long)bk1 * N + colTile + bc;

    float acc[2][8][4];
    #pragma unroll
    for (int i = 0; i < 2; i++)
        #pragma unroll
        for (int j = 0; j < 8; j++)
            #pragma unroll
            for (int r = 0; r < 4; r++) acc[i][j][r] = 0.f;

    const float4 zero4 = make_float4(0.f, 0.f, 0.f, 0.f);
    float4 av0, av1, bv0, bv1;

    // prologue: load k0 = 0
    av0 = aok0 ? *(const float4*)(Ap0) : zero4;
    av1 = aok1 ? *(const float4*)(Ap1) : zero4;
    bv0 = bok ? *(const float4*)(Bp0) : zero4;
    bv1 = bok ? *(const float4*)(Bp1) : zero4;

    const int kIters = K / GBK;

    #pragma unroll 1
    for (int it = 0; it < kIters; ++it) {
        const int buf = it & 1;
        // stage current regs -> smem[buf]
        if (!SPLIT) {  // pre-round to tf32 once
            av0.x = tf32f(av0.x); av0.y = tf32f(av0.y); av0.z = tf32f(av0.z); av0.w = tf32f(av0.w);
            av1.x = tf32f(av1.x); av1.y = tf32f(av1.y); av1.z = tf32f(av1.z); av1.w = tf32f(av1.w);
            bv0.x = tf32f(bv0.x); bv0.y = tf32f(bv0.y); bv0.z = tf32f(bv0.z); bv0.w = tf32f(bv0.w);
            bv1.x = tf32f(bv1.x); bv1.y = tf32f(bv1.y); bv1.z = tf32f(bv1.z); bv1.w = tf32f(bv1.w);
        }
        *(float4*)&As[buf][ar0][ac] = av0;
        *(float4*)&As[buf][ar1][ac] = av1;
        *(float4*)&Bs[buf][bk0][bc] = bv0;
        *(float4*)&Bs[buf][bk1][bc] = bv1;
        __syncthreads();

        // start next loads (overlap with compute)
        if (it + 1 < kIters) {
            const int k0 = (it + 1) * GBK;
            av0 = aok0 ? *(const float4*)(Ap0 + k0) : zero4;
            av1 = aok1 ? *(const float4*)(Ap1 + k0) : zero4;
            bv0 = bok ? *(const float4*)(Bp0 + (long)k0 * N) : zero4;
            bv1 = bok ? *(const float4*)(Bp1 + (long)k0 * N) : zero4;
        }

        // compute on smem[buf]
        #pragma unroll
        for (int kk = 0; kk < GBK; kk += 8) {
            float ar[2][4];
            #pragma unroll
            for (int mt = 0; mt < 2; mt++) {
                const int m0 = wm + mt * 16;
                ar[mt][0] = As[buf][m0 + g][kk + tig];
                ar[mt][1] = As[buf][m0 + g + 8][kk + tig];
                ar[mt][2] = As[buf][m0 + g][kk + tig + 4];
                ar[mt][3] = As[buf][m0 + g + 8][kk + tig + 4];
            }
            float br[8][2];
            #pragma unroll
            for (int nt = 0; nt < 8; nt++) {
                br[nt][0] = Bs[buf][kk + tig][wn + nt * 8 + g];
                br[nt][1] = Bs[buf][kk + tig + 4][wn + nt * 8 + g];
            }

            if (!SPLIT) {
                #pragma unroll
                for (int mt = 0; mt < 2; mt++)
                    #pragma unroll
                    for (int nt = 0; nt < 8; nt++)
                        mma8(acc[mt][nt],
                             __float_as_uint(ar[mt][0]), __float_as_uint(ar[mt][1]),
                             __float_as_uint(ar[mt][2]), __float_as_uint(ar[mt][3]),
                             __float_as_uint(br[nt][0]), __float_as_uint(br[nt][1]));
            } else {
                uint32_t ahi[2][4], alo[2][4];
                #pragma unroll
                for (int mt = 0; mt < 2; mt++)
                    #pragma unroll
                    for (int r = 0; r < 4; r++) {
                        float hi = tf32f(ar[mt][r]);
                        ahi[mt][r] = __float_as_uint(hi);
                        alo[mt][r] = f2tf32(ar[mt][r] - hi);
                    }
                uint32_t bhi[8][2], blo[8][2];
                #pragma unroll
                for (int nt = 0; nt < 8; nt++)
                    #pragma unroll
                    for (int r = 0; r < 2; r++) {
                        float hi = tf32f(br[nt][r]);
                        bhi[nt][r] = __float_as_uint(hi);
                        blo[nt][r] = f2tf32(br[nt][r] - hi);
                    }
                #pragma unroll
                for (int mt = 0; mt < 2; mt++)
                    #pragma unroll
                    for (int nt = 0; nt < 8; nt++) {
                        mma8(acc[mt][nt], ahi[mt][0], ahi[mt][1], ahi[mt][2], ahi[mt][3],
                             blo[nt][0], blo[nt][1]);
                        mma8(acc[mt][nt], alo[mt][0], alo[mt][1], alo[mt][2], alo[mt][3],
                             bhi[nt][0], bhi[nt][1]);
                        mma8(acc[mt][nt], ahi[mt][0], ahi[mt][1], ahi[mt][2], ahi[mt][3],
                             bhi[nt][0], bhi[nt][1]);
                    }
            }
        }
        __syncthreads();
    }

    // epilogue: bias + store (float2 per fragment row)
    #pragma unroll
    for (int mt = 0; mt < 2; mt++) {
        #pragma unroll
        for (int nt = 0; nt < 8; nt++) {
            const int c = colTile + wn + nt * 8 + tig * 2;
            if (c >= N) continue;
            const float b0 = bias[c], b1 = bias[c + 1];
            const int r0 = rowTile + wm + mt * 16 + g;
            if (r0 < M) {
                float2 v = make_float2(acc[mt][nt][0] + b0, acc[mt][nt][1] + b1);
                *(float2*)(C + (long)r0 * N + c) = v;
            }
            const int r1 = r0 + 8;
            if (r1 < M) {
                float2 v = make_float2(acc[mt][nt][2] + b0, acc[mt][nt][3] + b1);
                *(float2*)(C + (long)r1 * N + c) = v;
            }
        }
    }
}

// ---------------------------------------------------------------------------
// Concatenate W_off | W_attn into g_Wcat [256 x 96] and biases into g_bcat.
// ---------------------------------------------------------------------------
__global__ void prep_wcat_kernel(const float* __restrict__ W_off, const float* __restrict__ b_off,
                                 const float* __restrict__ W_attn, const float* __restrict__ b_attn)
{
    int i = blockIdx.x * blockDim.x + threadIdx.x;
    if (i < DMODEL * NPROJ) {
        int k = i / NPROJ, n = i % NPROJ;
        g_Wcat[i] = (n < 64) ? W_off[k * 64 + n] : W_attn[k * 32 + (n - 64)];
    }
    if (i < NPROJ) g_bcat[i] = (i < 64) ? b_off[i] : b_attn[i - 64];
}

// ---------------------------------------------------------------------------
// Sampler: softmax + bilinear gather only (projections precomputed in g_proj).
// One block per (b,q), 256 threads; warp == one head -> coalesced 128B lines.
// ---------------------------------------------------------------------------
__global__ __launch_bounds__(256) void deform_sample_kernel(
    const float* __restrict__ ref_pts,
    const int* __restrict__ hp, const int* __restrict__ wp,
    float* __restrict__ sampled)
{
    const int bq = blockIdx.x;
    const int tid = threadIdx.x;

    __shared__ float proj_sm[NPROJ];
    __shared__ float attn_sm[NHEADS * NPOINTS];
    __shared__ int   cx0[NHEADS * NPOINTS];
    __shared__ int   cy0[NHEADS * NPOINTS];
    __shared__ int   cx1[NHEADS * NPOINTS];
    __shared__ int   cy1[NHEADS * NPOINTS];
    __shared__ float cw00[NHEADS * NPOINTS];
    __shared__ float cw01[NHEADS * NPOINTS];
    __shared__ float cw10[NHEADS * NPOINTS];
    __shared__ float cw11[NHEADS * NPOINTS];

    if (tid < NPROJ) proj_sm[tid] = g_proj[(long)bq * NPROJ + tid];
    __syncthreads();

    // softmax over P, one thread per head
    if (tid < NHEADS) {
        float m = -1e30f;
        #pragma unroll
        for (int p = 0; p < NPOINTS; p++) m = fmaxf(m, proj_sm[64 + tid * NPOINTS + p]);
        float e[NPOINTS], s = 0.f;
        #pragma unroll
        for (int p = 0; p < NPOINTS; p++) {
            e[p] = expf(proj_sm[64 + tid * NPOINTS + p] - m);
            s += e[p];
        }
        float inv = 1.f / s;
        #pragma unroll
        for (int p = 0; p < NPOINTS; p++) attn_sm[tid * NPOINTS + p] = e[p] * inv;
    }

    // bilinear setup, one thread per (h,p)
    if (tid < NHEADS * NPOINTS) {
        const int ww = *wp;
        const int hh = *hp;
        float rx = ref_pts[(long)bq * 2 + 0];
        float ry = ref_pts[(long)bq * 2 + 1];
        float lx = fminf(fmaxf(rx + proj_sm[tid * 2 + 0], 0.f), 1.f);
        float ly = fminf(fmaxf(ry + proj_sm[tid * 2 + 1], 0.f), 1.f);
        float sx = lx * (float)(ww - 1);
        float sy = ly * (float)(hh - 1);
        int x0 = (int)floorf(sx); x0 = min(max(x0, 0), ww - 1);
        int y0 = (int)floorf(sy); y0 = min(max(y0, 0), hh - 1);
        int x1 = min(x0 + 1, ww - 1);
        int y1 = min(y0 + 1, hh - 1);
        float wx1 = sx - (float)x0, wx0 = 1.f - wx1;
        float wy1 = sy - (float)y0, wy0 = 1.f - wy1;
        cx0[tid] = x0; cy0[tid] = y0; cx1[tid] = x1; cy1[tid] = y1;
        cw00[tid] = wx0 * wy0;
        cw01[tid] = wx0 * wy1;
        cw10[tid] = wx1 * wy0;
        cw11[tid] = wx1 * wy1;
    }
    __syncthreads();

    // accumulate: thread = (head, channel); warp == head -> 128B lines
    const int head = tid >> 5;
    const int ch = tid & 31;
    const int b = bq / QLEN;
    const int ww = *wp;
    const float* vb = g_values + (long)b * HWTOT * DMODEL + head * DHEAD + ch;

    float acc = 0.f;
    #pragma unroll
    for (int p = 0; p < NPOINTS; p++) {
        int idx = head * NPOINTS + p;
        int x0 = cx0[idx], y0 = cy0[idx], x1 = cx1[idx], y1 = cy1[idx];
        float g00 = vb[(long)(y0 * ww + x0) * DMODEL];
        float g01 = vb[(long)(y1 * ww + x0) * DMODEL];
        float g10 = vb[(long)(y0 * ww + x1) * DMODEL];
        float g11 = vb[(long)(y1 * ww + x1) * DMODEL];
        float bl = g00 * cw00[idx] + g01 * cw01[idx] + g10 * cw10[idx] + g11 * cw11[idx];
        acc = fmaf(bl, attn_sm[idx], acc);
    }
    sampled[(long)bq * DMODEL + tid] = acc;
}

// ---------------------------------------------------------------------------
// Launch
// ---------------------------------------------------------------------------
extern "C" void kernel_launch(void* const* d_in, const int* in_sizes, int n_in,
                              void* d_out, int out_size)
{
    const float* query   = (const float*)d_in[0];
    const float* ref_pts = (const float*)d_in[1];
    const float* inp     = (const float*)d_in[2];
    const int*   hp      = (const int*)d_in[3];
    const int*   wp      = (const int*)d_in[4];
    const float* W_off   = (const float*)d_in[5];
    const float* b_off   = (const float*)d_in[6];
    const float* W_attn  = (const float*)d_in[7];
    const float* b_attn  = (const float*)d_in[8];
    const float* W_val   = (const float*)d_in[9];
    const float* b_val   = (const float*)d_in[10];
    const float* W_out   = (const float*)d_in[11];
    const float* b_out   = (const float*)d_in[12];
    float* out = (float*)d_out;

    float* values_ptr = nullptr;
    float* sampled_ptr = nullptr;
    float* proj_ptr = nullptr;
    float* wcat_ptr = nullptr;
    float* bcat_ptr = nullptr;
    cudaGetSymbolAddress((void**)&values_ptr, g_values);
    cudaGetSymbolAddress((void**)&sampled_ptr, g_sampled);
    cudaGetSymbolAddress((void**)&proj_ptr, g_proj);
    cudaGetSymbolAddress((void**)&wcat_ptr, g_Wcat);
    cudaGetSymbolAddress((void**)&bcat_ptr, g_bcat);

    const int M1 = BATCH * HWTOT;   // 80000
    const int MQ = BATCH * QLEN;    // 16384

    // 0) concat projection weights
    prep_wcat_kernel<<<(DMODEL * NPROJ + 255) / 256, 256>>>(W_off, b_off, W_attn, b_attn);

    // 1) values = input_flatten @ W_val + b_val   (single tf32: fast path)
    {
        dim3 grid(DMODEL / GBN, (M1 + GBM - 1) / GBM);
        tf32_gemm_kernel<false><<<grid, 256>>>(inp, W_val, b_val, values_ptr,
                                               M1, DMODEL, DMODEL);
    }

    // 2) proj = query @ [W_off|W_attn] + [b_off|b_attn]   (3xTF32: offsets are
    //    precision-critical — they get scaled by (w-1) pixels downstream)
    {
        dim3 grid(1, (MQ + GBM - 1) / GBM);
        tf32_gemm_kernel<true><<<grid, 256>>>(query, wcat_ptr, bcat_ptr, proj_ptr,
                                              MQ, NPROJ, DMODEL);
    }

    // 3) softmax + bilinear sampling
    deform_sample_kernel<<<BATCH * QLEN, 256>>>(ref_pts, hp, wp, sampled_ptr);

    // 4) out = sampled @ W_out + b_out   (3xTF32: keeps final error ~fp32)
    {
        dim3 grid(DMODEL / GBN, (MQ + GBM - 1) / GBM);
        tf32_gemm_kernel<true><<<grid, 256>>>(sampled_ptr, W_out, b_out, out,
                                              MQ, DMODEL, DMODEL);
    }
}

// round 3
// speedup vs baseline: 2.0415x; 1.0118x over previous
#include <cuda_runtime.h>
#include <cuda_bf16.h>
#include <math.h>
#include <stdint.h>

// Problem constants (fixed by the dataset instance)
#define NHEADS 8
#define NPOINTS 4
#define DMODEL 256
#define DHEAD 32
#define BATCH 8
#define QLEN 2048
#define HWTOT 10000
#define NPROJ 96   // 64 offset cols + 32 attn cols

// Scratch (device globals — no allocation allowed)
__device__ float g_values[(size_t)BATCH * HWTOT * DMODEL];   // 81.92 MB
__device__ float g_sampled[(size_t)BATCH * QLEN * DMODEL];   // 16.78 MB
__device__ float g_proj[(size_t)BATCH * QLEN * NPROJ];       //  6.29 MB
__device__ float g_Wcat[DMODEL * NPROJ];
__device__ float g_bcat[NPROJ];
__device__ int   g_tidx[(size_t)BATCH * QLEN * NHEADS * 16]; // 8.39 MB
__device__ float g_tw[(size_t)BATCH * QLEN * NHEADS * 16];   // 8.39 MB

// ---------------------------------------------------------------------------
// helpers
// ---------------------------------------------------------------------------
__device__ __forceinline__ uint32_t f2tf32(float x) {
    uint32_t u;
    asm("cvt.rna.tf32.f32 %0, %1;" : "=r"(u) : "f"(x));
    return u;
}
__device__ __forceinline__ float tf32f(float x) {
    return __uint_as_float(f2tf32(x));
}

__device__ __forceinline__ void mma8(float d[4],
                                     uint32_t a0, uint32_t a1, uint32_t a2, uint32_t a3,
                                     uint32_t b0, uint32_t b1) {
    asm volatile(
        "mma.sync.aligned.m16n8k8.row.col.f32.tf32.tf32.f32 "
        "{%0,%1,%2,%3}, {%4,%5,%6,%7}, {%8,%9}, {%0,%1,%2,%3};"
        : "+f"(d[0]), "+f"(d[1]), "+f"(d[2]), "+f"(d[3])
        : "r"(a0), "r"(a1), "r"(a2), "r"(a3), "r"(b0), "r"(b1));
}

__device__ __forceinline__ void cpasync16(uint32_t smem_addr, const void* gptr, bool valid) {
    int sz = valid ? 16 : 0;
    asm volatile("cp.async.cg.shared.global [%0], [%1], 16, %2;\n"
                 :: "r"(smem_addr), "l"(gptr), "r"(sz));
}
__device__ __forceinline__ void cpasync_commit() {
    asm volatile("cp.async.commit_group;\n" ::);
}
template<int N>
__device__ __forceinline__ void cpasync_wait() {
    asm volatile("cp.async.wait_group %0;\n" :: "n"(N));
}

// ---------------------------------------------------------------------------
// TF32 tensor-core GEMM with 4-stage cp.async pipeline.
// C[M,N] = A[M,K] @ B[K,N] + bias[N], row-major fp32.
// Block tile 128x128x16, 256 threads (8 warps as 4x2), warp tile 32x64.
// SPLIT=true -> 3xTF32 (hi/lo) for fp32-level accuracy.
// Requires K % 16 == 0, N % 4 == 0.
// ---------------------------------------------------------------------------
#define GBM 128
#define GBN 128
#define GBK 16
#define STAGES 4
#define AS_STRIDE 20    // [m][k] padded
#define BS_STRIDE 132   // [k][n] padded
#define GEMM_SMEM_BYTES (STAGES * (GBM * AS_STRIDE + GBK * BS_STRIDE) * 4)

template<bool SPLIT>
__global__ __launch_bounds__(256) void tf32_gemm_kernel(
    const float* __restrict__ A, const float* __restrict__ B,
    const float* __restrict__ bias, float* __restrict__ C,
    int M, int N, int K)
{
    extern __shared__ __align__(16) float dsm[];
    float* As = dsm;                                  // [STAGES][GBM][AS_STRIDE]
    float* Bs = dsm + STAGES * GBM * AS_STRIDE;       // [STAGES][GBK][BS_STRIDE]

    const int t = threadIdx.x;
    const int warp = t >> 5;
    const int lane = t & 31;
    const int g = lane >> 2;    // 0..7
    const int tig = lane & 3;   // 0..3
    const int wm = (warp >> 1) * 32;
    const int wn = (warp & 1) * 64;

    const int rowTile = blockIdx.y * GBM;
    const int colTile = blockIdx.x * GBN;

    // loader mapping: per tile each thread moves 2 A float4 + 2 B float4
    const int ar0 = t >> 2;            // 0..63
    const int ar1 = ar0 + 64;          // 64..127
    const int ac = (t & 3) * 4;        // {0,4,8,12}
    const int bk0 = t >> 5;            // 0..7
    const int bk1 = bk0 + 8;           // 8..15
    const int bc = (t & 31) * 4;       // 0..124

    const bool aok0 = (rowTile + ar0) < M;
    const bool aok1 = (rowTile + ar1) < M;
    const bool bok = (colTile + bc) < N;

    const float* Ap0 = A + (long)(rowTile + ar0) * K + ac;
    const float* Ap1 = A + (long)(rowTile + ar1) * K + ac;
    const float* Bp0 = B + (long)bk0 * N + colTile + bc;
    const float* Bp1 = B + (long)bk1 * N + colTile + bc;

    const uint32_t aStageB = GBM * AS_STRIDE * 4;
    const uint32_t bStageB = GBK * BS_STRIDE * 4;
    const uint32_t sA0 = (uint32_t)__cvta_generic_to_shared(As + ar0 * AS_STRIDE + ac);
    const uint32_t sA1 = (uint32_t)__cvta_generic_to_shared(As + ar1 * AS_STRIDE + ac);
    const uint32_t sB0 = (uint32_t)__cvta_generic_to_shared(Bs + bk0 * BS_STRIDE + bc);
    const uint32_t sB1 = (uint32_t)__cvta_generic_to_shared(Bs + bk1 * BS_STRIDE + bc);

    const int kIters = K / GBK;

    auto issue_tile = [&](int tile) {
        if (tile < kIters) {
            const int s = tile % STAGES;
            const long k0 = (long)tile * GBK;
            cpasync16(sA0 + s * aStageB, Ap0 + k0, aok0);
            cpasync16(sA1 + s * aStageB, Ap1 + k0, aok1);
            cpasync16(sB0 + s * bStageB, Bp0 + k0 * N, bok);
            cpasync16(sB1 + s * bStageB, Bp1 + k0 * N, bok);
        }
        cpasync_commit();
    };

    float acc[2][8][4];
    #pragma unroll
    for (int i = 0; i < 2; i++)
        #pragma unroll
        for (int j = 0; j < 8; j++)
            #pragma unroll
            for (int r = 0; r < 4; r++) acc[i][j][r] = 0.f;

    // prologue: stages 0..STAGES-2
    #pragma unroll
    for (int s = 0; s < STAGES - 1; s++) issue_tile(s);

    #pragma unroll 1
    for (int it = 0; it < kIters; ++it) {
        cpasync_wait<STAGES - 2>();
        __syncthreads();          // tile `it` resident; all threads done with it-1

        issue_tile(it + STAGES - 1);   // fills buffer (it-1)%STAGES — free now

        const int s = it % STAGES;
        const float* AsS = As + s * GBM * AS_STRIDE;
        const float* BsS = Bs + s * GBK * BS_STRIDE;

        #pragma unroll
        for (int kk = 0; kk < GBK; kk += 8) {
            float ar[2][4];
            #pragma unroll
            for (int mt = 0; mt < 2; mt++) {
                const int m0 = wm + mt * 16;
                ar[mt][0] = AsS[(m0 + g) * AS_STRIDE + kk + tig];
                ar[mt][1] = AsS[(m0 + g + 8) * AS_STRIDE + kk + tig];
                ar[mt][2] = AsS[(m0 + g) * AS_STRIDE + kk + tig + 4];
                ar[mt][3] = AsS[(m0 + g + 8) * AS_STRIDE + kk + tig + 4];
            }
            float br[8][2];
            #pragma unroll
            for (int nt = 0; nt < 8; nt++) {
                br[nt][0] = BsS[(kk + tig) * BS_STRIDE + wn + nt * 8 + g];
                br[nt][1] = BsS[(kk + tig + 4) * BS_STRIDE + wn + nt * 8 + g];
            }

            if (!SPLIT) {
                uint32_t au[2][4], bu[8][2];
                #pragma unroll
                for (int mt = 0; mt < 2; mt++)
                    #pragma unroll
                    for (int r = 0; r < 4; r++) au[mt][r] = f2tf32(ar[mt][r]);
                #pragma unroll
                for (int nt = 0; nt < 8; nt++)
                    #pragma unroll
                    for (int r = 0; r < 2; r++) bu[nt][r] = f2tf32(br[nt][r]);
                #pragma unroll
                for (int mt = 0; mt < 2; mt++)
                    #pragma unroll
                    for (int nt = 0; nt < 8; nt++)
                        mma8(acc[mt][nt], au[mt][0], au[mt][1], au[mt][2], au[mt][3],
                             bu[nt][0], bu[nt][1]);
            } else {
                uint32_t ahi[2][4], alo[2][4];
                #pragma unroll
                for (int mt = 0; mt < 2; mt++)
                    #pragma unroll
                    for (int r = 0; r < 4; r++) {
                        float hi = tf32f(ar[mt][r]);
                        ahi[mt][r] = __float_as_uint(hi);
                        alo[mt][r] = f2tf32(ar[mt][r] - hi);
                    }
                uint32_t bhi[8][2], blo[8][2];
                #pragma unroll
                for (int nt = 0; nt < 8; nt++)
                    #pragma unroll
                    for (int r = 0; r < 2; r++) {
                        float hi = tf32f(br[nt][r]);
                        bhi[nt][r] = __float_as_uint(hi);
                        blo[nt][r] = f2tf32(br[nt][r] - hi);
                    }
                #pragma unroll
                for (int mt = 0; mt < 2; mt++)
                    #pragma unroll
                    for (int nt = 0; nt < 8; nt++) {
                        mma8(acc[mt][nt], ahi[mt][0], ahi[mt][1], ahi[mt][2], ahi[mt][3],
                             blo[nt][0], blo[nt][1]);
                        mma8(acc[mt][nt], alo[mt][0], alo[mt][1], alo[mt][2], alo[mt][3],
                             bhi[nt][0], bhi[nt][1]);
                        mma8(acc[mt][nt], ahi[mt][0], ahi[mt][1], ahi[mt][2], ahi[mt][3],
                             bhi[nt][0], bhi[nt][1]);
                    }
            }
        }
    }

    // epilogue: bias + store (float2 per fragment row)
    #pragma unroll
    for (int mt = 0; mt < 2; mt++) {
        #pragma unroll
        for (int nt = 0; nt < 8; nt++) {
            const int c = colTile + wn + nt * 8 + tig * 2;
            if (c >= N) continue;
            const float b0 = bias[c], b1 = bias[c + 1];
            const int r0 = rowTile + wm + mt * 16 + g;
            if (r0 < M) {
                float2 v = make_float2(acc[mt][nt][0] + b0, acc[mt][nt][1] + b1);
                *(float2*)(C + (long)r0 * N + c) = v;
            }
            const int r1 = r0 + 8;
            if (r1 < M) {
                float2 v = make_float2(acc[mt][nt][2] + b0, acc[mt][nt][3] + b1);
                *(float2*)(C + (long)r1 * N + c) = v;
            }
        }
    }
}

// ---------------------------------------------------------------------------
// Concatenate W_off | W_attn into g_Wcat [256 x 96] and biases into g_bcat.
// ---------------------------------------------------------------------------
__global__ void prep_wcat_kernel(const float* __restrict__ W_off, const float* __restrict__ b_off,
                                 const float* __restrict__ W_attn, const float* __restrict__ b_attn)
{
    int i = blockIdx.x * blockDim.x + threadIdx.x;
    if (i < DMODEL * NPROJ) {
        int k = i / NPROJ, n = i % NPROJ;
        g_Wcat[i] = (n < 64) ? W_off[k * 64 + n] : W_attn[k * 32 + (n - 64)];
    }
    if (i < NPROJ) g_bcat[i] = (i < 64) ? b_off[i] : b_attn[i - 64];
}

// ---------------------------------------------------------------------------
// Prep: per (bq, head) — softmax over points, bilinear corner indices and
// combined (bilinear * attn) weights -> g_tidx / g_tw (16 pairs each).
// ---------------------------------------------------------------------------
__global__ __launch_bounds__(256) void prep_tab_kernel(
    const float* __restrict__ ref_pts,
    const int* __restrict__ hp, const int* __restrict__ wp)
{
    const int t = blockIdx.x * blockDim.x + threadIdx.x;   // bq*8 + h
    if (t >= BATCH * QLEN * NHEADS) return;
    const int bq = t >> 3;
    const int h = t & 7;
    const int b = bq / QLEN;

    const float* pr = g_proj + (long)bq * NPROJ;

    // softmax over the 4 points of this head
    float l0 = pr[64 + h * 4 + 0];
    float l1 = pr[64 + h * 4 + 1];
    float l2 = pr[64 + h * 4 + 2];
    float l3 = pr[64 + h * 4 + 3];
    float m = fmaxf(fmaxf(l0, l1), fmaxf(l2, l3));
    float e0 = expf(l0 - m), e1 = expf(l1 - m), e2 = expf(l2 - m), e3 = expf(l3 - m);
    float inv = 1.f / (e0 + e1 + e2 + e3);
    float attn[NPOINTS] = { e0 * inv, e1 * inv, e2 * inv, e3 * inv };

    const int ww = *wp;
    const int hh = *hp;
    const float rx = ref_pts[(long)bq * 2 + 0];
    const float ry = ref_pts[(long)bq * 2 + 1];
    const int vbase = b * HWTOT * DMODEL + h * DHEAD;

    int* ti = g_tidx + (long)t * 16;
    float* tw = g_tw + (long)t * 16;

    #pragma unroll
    for (int p = 0; p < NPOINTS; p++) {
        const int hp4 = h * NPOINTS + p;
        float lx = fminf(fmaxf(rx + pr[hp4 * 2 + 0], 0.f), 1.f);
        float ly = fminf(fmaxf(ry + pr[hp4 * 2 + 1], 0.f), 1.f);
        float sx = lx * (float)(ww - 1);
        float sy = ly * (float)(hh - 1);
        int x0 = (int)floorf(sx); x0 = min(max(x0, 0), ww - 1);
        int y0 = (int)floorf(sy); y0 = min(max(y0, 0), hh - 1);
        int x1 = min(x0 + 1, ww - 1);
        int y1 = min(y0 + 1, hh - 1);
        float wx1 = sx - (float)x0, wx0 = 1.f - wx1;
        float wy1 = sy - (float)y0, wy0 = 1.f - wy1;
        float a = attn[p];
        ti[p * 4 + 0] = vbase + (y0 * ww + x0) * DMODEL;
        ti[p * 4 + 1] = vbase + (y1 * ww + x0) * DMODEL;
        ti[p * 4 + 2] = vbase + (y0 * ww + x1) * DMODEL;
        ti[p * 4 + 3] = vbase + (y1 * ww + x1) * DMODEL;
        tw[p * 4 + 0] = wx0 * wy0 * a;
        tw[p * 4 + 1] = wx0 * wy1 * a;
        tw[p * 4 + 2] = wx1 * wy0 * a;
        tw[p * 4 + 3] = wx1 * wy1 * a;
    }
}

// ---------------------------------------------------------------------------
// Gather: warp = (bq, head), lane = channel. 16 independent coalesced 128B
// gathers per lane; no smem, no barriers.
// ---------------------------------------------------------------------------
__global__ __launch_bounds__(256) void gather_kernel(float* __restrict__ sampled)
{
    const int wg = (blockIdx.x * blockDim.x + threadIdx.x) >> 5;   // bq*8 + h
    const int lane = threadIdx.x & 31;
    if (wg >= BATCH * QLEN * NHEADS) return;

    const int4* ti = (const int4*)(g_tidx + (long)wg * 16);
    const float4* tw = (const float4*)(g_tw + (long)wg * 16);

    float acc = 0.f;
    #pragma unroll
    for (int c = 0; c < 4; c++) {
        int4 id = ti[c];
        float4 w = tw[c];
        acc = fmaf(w.x, g_values[id.x + lane], acc);
        acc = fmaf(w.y, g_values[id.y + lane], acc);
        acc = fmaf(w.z, g_values[id.z + lane], acc);
        acc = fmaf(w.w, g_values[id.w + lane], acc);
    }

    const int bq = wg >> 3;
    const int h = wg & 7;
    sampled[(long)bq * DMODEL + h * DHEAD + lane] = acc;
}

// ---------------------------------------------------------------------------
// Launch
// ---------------------------------------------------------------------------
extern "C" void kernel_launch(void* const* d_in, const int* in_sizes, int n_in,
                              void* d_out, int out_size)
{
    const float* query   = (const float*)d_in[0];
    const float* ref_pts = (const float*)d_in[1];
    const float* inp     = (const float*)d_in[2];
    const int*   hp      = (const int*)d_in[3];
    const int*   wp      = (const int*)d_in[4];
    const float* W_off   = (const float*)d_in[5];
    const float* b_off   = (const float*)d_in[6];
    const float* W_attn  = (const float*)d_in[7];
    const float* b_attn  = (const float*)d_in[8];
    const float* W_val   = (const float*)d_in[9];
    const float* b_val   = (const float*)d_in[10];
    const float* W_out   = (const float*)d_in[11];
    const float* b_out   = (const float*)d_in[12];
    float* out = (float*)d_out;

    float* values_ptr = nullptr;
    float* sampled_ptr = nullptr;
    float* proj_ptr = nullptr;
    float* wcat_ptr = nullptr;
    float* bcat_ptr = nullptr;
    cudaGetSymbolAddress((void**)&values_ptr, g_values);
    cudaGetSymbolAddress((void**)&sampled_ptr, g_sampled);
    cudaGetSymbolAddress((void**)&proj_ptr, g_proj);
    cudaGetSymbolAddress((void**)&wcat_ptr, g_Wcat);
    cudaGetSymbolAddress((void**)&bcat_ptr, g_bcat);

    static bool attr_done = false;
    if (!attr_done) {
        cudaFuncSetAttribute(tf32_gemm_kernel<false>,
                             cudaFuncAttributeMaxDynamicSharedMemorySize, GEMM_SMEM_BYTES);
        cudaFuncSetAttribute(tf32_gemm_kernel<true>,
                             cudaFuncAttributeMaxDynamicSharedMemorySize, GEMM_SMEM_BYTES);
        attr_done = true;
    }

    const int M1 = BATCH * HWTOT;   // 80000
    const int MQ = BATCH * QLEN;    // 16384

    // 0) concat projection weights
    prep_wcat_kernel<<<(DMODEL * NPROJ + 255) / 256, 256>>>(W_off, b_off, W_attn, b_attn);

    // 1) values = input_flatten @ W_val + b_val   (single tf32)
    {
        dim3 grid(DMODEL / GBN, (M1 + GBM - 1) / GBM);
        tf32_gemm_kernel<false><<<grid, 256, GEMM_SMEM_BYTES>>>(
            inp, W_val, b_val, values_ptr, M1, DMODEL, DMODEL);
    }

    // 2) proj = query @ [W_off|W_attn] + bias   (3xTF32: precision-critical)
    {
        dim3 grid(1, (MQ + GBM - 1) / GBM);
        tf32_gemm_kernel<true><<<grid, 256, GEMM_SMEM_BYTES>>>(
            query, wcat_ptr, bcat_ptr, proj_ptr, MQ, NPROJ, DMODEL);
    }

    // 3a) softmax + bilinear table
    prep_tab_kernel<<<(BATCH * QLEN * NHEADS + 255) / 256, 256>>>(ref_pts, hp, wp);

    // 3b) gather
    gather_kernel<<<(BATCH * QLEN * NHEADS) / 8, 256>>>(sampled_ptr);

    // 4) out = sampled @ W_out + b_out   (3xTF32)
    {
        dim3 grid(DMODEL / GBN, (MQ + GBM - 1) / GBM);
        tf32_gemm_kernel<true><<<grid, 256, GEMM_SMEM_BYTES>>>(
            sampled_ptr, W_out, b_out, out, MQ, DMODEL, DMODEL);
    }
}

// round 5
// speedup vs baseline: 2.4505x; 1.2003x over previous
#include <cuda_runtime.h>
#include <cuda_fp16.h>
#include <math.h>
#include <stdint.h>

// Problem constants (fixed by the dataset instance)
#define NHEADS 8
#define NPOINTS 4
#define DMODEL 256
#define DHEAD 32
#define BATCH 8
#define QLEN 2048
#define HWTOT 10000
#define NPROJ 96   // 64 offset cols + 32 attn cols

// Scratch (device globals — no allocation allowed)
__device__ float g_values[(size_t)BATCH * HWTOT * DMODEL];   // 81.92 MB
__device__ float g_sampled[(size_t)BATCH * QLEN * DMODEL];   // 16.78 MB
__device__ float g_proj[(size_t)BATCH * QLEN * NPROJ];       //  6.29 MB
__device__ float g_Wcat[DMODEL * NPROJ];
__device__ float g_bcat[NPROJ];
__device__ float g_WvalT[DMODEL * DMODEL];
__device__ float g_WoutT[DMODEL * DMODEL];
__device__ int   g_tidx[(size_t)BATCH * QLEN * NHEADS * 16];
__device__ float g_tw[(size_t)BATCH * QLEN * NHEADS * 16];

// ---------------------------------------------------------------------------
// helpers
// ---------------------------------------------------------------------------
__device__ __forceinline__ uint32_t f2tf32(float x) {
    uint32_t u;
    asm("cvt.rna.tf32.f32 %0, %1;" : "=r"(u) : "f"(x));
    return u;
}
__device__ __forceinline__ float tf32f(float x) {
    return __uint_as_float(f2tf32(x));
}

// fp16 mma: D += A(16x16) * B(16x8), fp32 accum
__device__ __forceinline__ void mma16816(float d[4],
                                         uint32_t a0, uint32_t a1, uint32_t a2, uint32_t a3,
                                         uint32_t b0, uint32_t b1) {
    asm volatile(
        "mma.sync.aligned.m16n8k16.row.col.f32.f16.f16.f32 "
        "{%0,%1,%2,%3}, {%4,%5,%6,%7}, {%8,%9}, {%0,%1,%2,%3};"
        : "+f"(d[0]), "+f"(d[1]), "+f"(d[2]), "+f"(d[3])
        : "r"(a0), "r"(a1), "r"(a2), "r"(a3), "r"(b0), "r"(b1));
}
// tf32 mma: D += A(16x8) * B(8x8)
__device__ __forceinline__ void mma8(float d[4],
                                     uint32_t a0, uint32_t a1, uint32_t a2, uint32_t a3,
                                     uint32_t b0, uint32_t b1) {
    asm volatile(
        "mma.sync.aligned.m16n8k8.row.col.f32.tf32.tf32.f32 "
        "{%0,%1,%2,%3}, {%4,%5,%6,%7}, {%8,%9}, {%0,%1,%2,%3};"
        : "+f"(d[0]), "+f"(d[1]), "+f"(d[2]), "+f"(d[3])
        : "r"(a0), "r"(a1), "r"(a2), "r"(a3), "r"(b0), "r"(b1));
}
__device__ __forceinline__ void cpasync16(uint32_t smem_addr, const void* gptr, bool valid) {
    int sz = valid ? 16 : 0;
    asm volatile("cp.async.cg.shared.global [%0], [%1], 16, %2;\n"
                 :: "r"(smem_addr), "l"(gptr), "r"(sz));
}
__device__ __forceinline__ void cpasync_commit() {
    asm volatile("cp.async.commit_group;\n" ::);
}
template<int Ncp>
__device__ __forceinline__ void cpasync_wait() {
    asm volatile("cp.async.wait_group %0;\n" :: "n"(Ncp));
}

// ---------------------------------------------------------------------------
// FP16 tensor-core GEMM: C[M,N] = A[M,K] @ BT^T + bias  (BT is [N,K] row-major,
// both fp32 in gmem; converted to fp16 in the loader; fp32 accumulate).
// Block tile 128x128x32, 256 threads (8 warps 4x2), warp tile 32x64.
// Requires M%128==0, N%128==0, K%32==0.
// Both operands stored K-major in smem -> every mma fragment is one half2.
// ---------------------------------------------------------------------------
#define HBM_ 128
#define HBN_ 128
#define HBK_ 32
#define HSTR 40     // halfs per smem row (32 + 8 pad): conflict-free frag reads

__global__ __launch_bounds__(256) void fp16_gemm_kernel(
    const float* __restrict__ A, const float* __restrict__ BT,
    const float* __restrict__ bias, float* __restrict__ C,
    int M, int N, int K)
{
    __shared__ __align__(16) __half As[2][HBM_][HSTR];
    __shared__ __align__(16) __half Bs[2][HBN_][HSTR];

    const int t = threadIdx.x;
    const int warp = t >> 5;
    const int lane = t & 31;
    const int g = lane >> 2;     // 0..7
    const int tig = lane & 3;    // 0..3
    const int wm = (warp >> 1) * 32;   // warp m offset
    const int wn = (warp & 1) * 64;    // warp n offset

    const int rowTile = blockIdx.y * HBM_;
    const int colTile = blockIdx.x * HBN_;

    // loader: tile = 128 rows x 8 float4 (32 floats); 1024 float4 / 256 thr = 4 each
    // idx = t + j*256 -> row = idx>>3, fc = idx&7
    const float* Ag = A + (long)rowTile * K;
    const float* Bg = BT + (long)colTile * K;

    float4 abuf[4], bbuf[4];
    auto load_regs = [&](int k0) {
        #pragma unroll
        for (int j = 0; j < 4; j++) {
            const int idx = t + j * 256;
            const int r = idx >> 3;
            const int fc = idx & 7;
            abuf[j] = *(const float4*)(Ag + (long)r * K + k0 + fc * 4);
            bbuf[j] = *(const float4*)(Bg + (long)r * K + k0 + fc * 4);
        }
    };
    auto store_smem = [&](int buf) {
        #pragma unroll
        for (int j = 0; j < 4; j++) {
            const int idx = t + j * 256;
            const int r = idx >> 3;
            const int fc = idx & 7;
            __half2 a01 = __floats2half2_rn(abuf[j].x, abuf[j].y);
            __half2 a23 = __floats2half2_rn(abuf[j].z, abuf[j].w);
            *(__half2*)&As[buf][r][fc * 4 + 0] = a01;
            *(__half2*)&As[buf][r][fc * 4 + 2] = a23;
            __half2 b01 = __floats2half2_rn(bbuf[j].x, bbuf[j].y);
            __half2 b23 = __floats2half2_rn(bbuf[j].z, bbuf[j].w);
            *(__half2*)&Bs[buf][r][fc * 4 + 0] = b01;
            *(__half2*)&Bs[buf][r][fc * 4 + 2] = b23;
        }
    };

    float acc[2][8][4];
    #pragma unroll
    for (int i = 0; i < 2; i++)
        #pragma unroll
        for (int j = 0; j < 8; j++)
            #pragma unroll
            for (int r = 0; r < 4; r++) acc[i][j][r] = 0.f;

    const int kIters = K / HBK_;
    load_regs(0);

    #pragma unroll 1
    for (int it = 0; it < kIters; ++it) {
        const int buf = it & 1;
        store_smem(buf);
        __syncthreads();
        if (it + 1 < kIters) load_regs((it + 1) * HBK_);

        #pragma unroll
        for (int ks = 0; ks < 2; ks++) {       // two k16 steps per 32-k tile
            const int kb = ks * 16;
            uint32_t af[2][4];
            #pragma unroll
            for (int mt = 0; mt < 2; mt++) {
                const int m0 = wm + mt * 16;
                af[mt][0] = *(const uint32_t*)&As[buf][m0 + g][kb + 2 * tig];
                af[mt][1] = *(const uint32_t*)&As[buf][m0 + g + 8][kb + 2 * tig];
                af[mt][2] = *(const uint32_t*)&As[buf][m0 + g][kb + 2 * tig + 8];
                af[mt][3] = *(const uint32_t*)&As[buf][m0 + g + 8][kb + 2 * tig + 8];
            }
            uint32_t bf[8][2];
            #pragma unroll
            for (int nt = 0; nt < 8; nt++) {
                const int n0 = wn + nt * 8;
                bf[nt][0] = *(const uint32_t*)&Bs[buf][n0 + g][kb + 2 * tig];
                bf[nt][1] = *(const uint32_t*)&Bs[buf][n0 + g][kb + 2 * tig + 8];
            }
            #pragma unroll
            for (int mt = 0; mt < 2; mt++)
                #pragma unroll
                for (int nt = 0; nt < 8; nt++)
                    mma16816(acc[mt][nt], af[mt][0], af[mt][1], af[mt][2], af[mt][3],
                             bf[nt][0], bf[nt][1]);
        }
        __syncthreads();
    }

    // epilogue: bias + float2 stores
    #pragma unroll
    for (int mt = 0; mt < 2; mt++) {
        #pragma unroll
        for (int nt = 0; nt < 8; nt++) {
            const int c = colTile + wn + nt * 8 + tig * 2;
            const float b0 = bias[c], b1 = bias[c + 1];
            const int r0 = rowTile + wm + mt * 16 + g;
            float2 v0 = make_float2(acc[mt][nt][0] + b0, acc[mt][nt][1] + b1);
            *(float2*)(C + (long)r0 * N + c) = v0;
            float2 v1 = make_float2(acc[mt][nt][2] + b0, acc[mt][nt][3] + b1);
            *(float2*)(C + (long)(r0 + 8) * N + c) = v1;
        }
    }
}

// ---------------------------------------------------------------------------
// mma.sync 3xTF32 split GEMM (precision-critical offset/attn projection only).
// ---------------------------------------------------------------------------
#define GBM 128
#define GBN 128
#define GBK 16
#define STAGES 4
#define AS_STRIDE 20
#define BS_STRIDE 132
#define GEMM_SMEM_BYTES (STAGES * (GBM * AS_STRIDE + GBK * BS_STRIDE) * 4)

__global__ __launch_bounds__(256) void tf32_split_gemm_kernel(
    const float* __restrict__ A, const float* __restrict__ B,
    const float* __restrict__ bias, float* __restrict__ C,
    int M, int N, int K)
{
    extern __shared__ __align__(16) float dsmf[];
    float* As = dsmf;
    float* Bs = dsmf + STAGES * GBM * AS_STRIDE;

    const int t = threadIdx.x;
    const int warp = t >> 5;
    const int lane = t & 31;
    const int g = lane >> 2;
    const int tig = lane & 3;
    const int wm = (warp >> 1) * 32;
    const int wn = (warp & 1) * 64;

    const int rowTile = blockIdx.y * GBM;
    const int colTile = blockIdx.x * GBN;

    const int ar0 = t >> 2;
    const int ar1 = ar0 + 64;
    const int ac = (t & 3) * 4;
    const int bk0 = t >> 5;
    const int bk1 = bk0 + 8;
    const int bc = (t & 31) * 4;

    const bool aok0 = (rowTile + ar0) < M;
    const bool aok1 = (rowTile + ar1) < M;
    const bool bok = (colTile + bc) < N;

    const float* Ap0 = A + (long)(rowTile + ar0) * K + ac;
    const float* Ap1 = A + (long)(rowTile + ar1) * K + ac;
    const float* Bp0 = B + (long)bk0 * N + colTile + bc;
    const float* Bp1 = B + (long)bk1 * N + colTile + bc;

    const uint32_t aStageB = GBM * AS_STRIDE * 4;
    const uint32_t bStageB = GBK * BS_STRIDE * 4;
    const uint32_t sA0 = (uint32_t)__cvta_generic_to_shared(As + ar0 * AS_STRIDE + ac);
    const uint32_t sA1 = (uint32_t)__cvta_generic_to_shared(As + ar1 * AS_STRIDE + ac);
    const uint32_t sB0 = (uint32_t)__cvta_generic_to_shared(Bs + bk0 * BS_STRIDE + bc);
    const uint32_t sB1 = (uint32_t)__cvta_generic_to_shared(Bs + bk1 * BS_STRIDE + bc);

    const int kIters = K / GBK;

    auto issue_tile = [&](int tile) {
        if (tile < kIters) {
            const int s = tile % STAGES;
            const long k0 = (long)tile * GBK;
            cpasync16(sA0 + s * aStageB, Ap0 + k0, aok0);
            cpasync16(sA1 + s * aStageB, Ap1 + k0, aok1);
            cpasync16(sB0 + s * bStageB, Bp0 + k0 * N, bok);
            cpasync16(sB1 + s * bStageB, Bp1 + k0 * N, bok);
        }
        cpasync_commit();
    };

    float acc[2][8][4];
    #pragma unroll
    for (int i = 0; i < 2; i++)
        #pragma unroll
        for (int j = 0; j < 8; j++)
            #pragma unroll
            for (int r = 0; r < 4; r++) acc[i][j][r] = 0.f;

    #pragma unroll
    for (int s = 0; s < STAGES - 1; s++) issue_tile(s);

    #pragma unroll 1
    for (int it = 0; it < kIters; ++it) {
        cpasync_wait<STAGES - 2>();
        __syncthreads();
        issue_tile(it + STAGES - 1);

        const int s = it % STAGES;
        const float* AsS = As + s * GBM * AS_STRIDE;
        const float* BsS = Bs + s * GBK * BS_STRIDE;

        #pragma unroll
        for (int kk = 0; kk < GBK; kk += 8) {
            float ar[2][4];
            #pragma unroll
            for (int mt = 0; mt < 2; mt++) {
                const int m0 = wm + mt * 16;
                ar[mt][0] = AsS[(m0 + g) * AS_STRIDE + kk + tig];
                ar[mt][1] = AsS[(m0 + g + 8) * AS_STRIDE + kk + tig];
                ar[mt][2] = AsS[(m0 + g) * AS_STRIDE + kk + tig + 4];
                ar[mt][3] = AsS[(m0 + g + 8) * AS_STRIDE + kk + tig + 4];
            }
            float br[8][2];
            #pragma unroll
            for (int nt = 0; nt < 8; nt++) {
                br[nt][0] = BsS[(kk + tig) * BS_STRIDE + wn + nt * 8 + g];
                br[nt][1] = BsS[(kk + tig + 4) * BS_STRIDE + wn + nt * 8 + g];
            }
            uint32_t ahi[2][4], alo[2][4];
            #pragma unroll
            for (int mt = 0; mt < 2; mt++)
                #pragma unroll
                for (int r = 0; r < 4; r++) {
                    float hi = tf32f(ar[mt][r]);
                    ahi[mt][r] = __float_as_uint(hi);
                    alo[mt][r] = f2tf32(ar[mt][r] - hi);
                }
            uint32_t bhi[8][2], blo[8][2];
            #pragma unroll
            for (int nt = 0; nt < 8; nt++)
                #pragma unroll
                for (int r = 0; r < 2; r++) {
                    float hi = tf32f(br[nt][r]);
                    bhi[nt][r] = __float_as_uint(hi);
                    blo[nt][r] = f2tf32(br[nt][r] - hi);
                }
            #pragma unroll
            for (int mt = 0; mt < 2; mt++)
                #pragma unroll
                for (int nt = 0; nt < 8; nt++) {
                    mma8(acc[mt][nt], ahi[mt][0], ahi[mt][1], ahi[mt][2], ahi[mt][3],
                         blo[nt][0], blo[nt][1]);
                    mma8(acc[mt][nt], alo[mt][0], alo[mt][1], alo[mt][2], alo[mt][3],
                         bhi[nt][0], bhi[nt][1]);
                    mma8(acc[mt][nt], ahi[mt][0], ahi[mt][1], ahi[mt][2], ahi[mt][3],
                         bhi[nt][0], bhi[nt][1]);
                }
        }
    }

    #pragma unroll
    for (int mt = 0; mt < 2; mt++) {
        #pragma unroll
        for (int nt = 0; nt < 8; nt++) {
            const int c = colTile + wn + nt * 8 + tig * 2;
            if (c >= N) continue;
            const float b0 = bias[c], b1 = bias[c + 1];
            const int r0 = rowTile + wm + mt * 16 + g;
            if (r0 < M) {
                float2 v = make_float2(acc[mt][nt][0] + b0, acc[mt][nt][1] + b1);
                *(float2*)(C + (long)r0 * N + c) = v;
            }
            const int r1 = r0 + 8;
            if (r1 < M) {
                float2 v = make_float2(acc[mt][nt][2] + b0, acc[mt][nt][3] + b1);
                *(float2*)(C + (long)r1 * N + c) = v;
            }
        }
    }
}

// ---------------------------------------------------------------------------
// Prep kernels
// ---------------------------------------------------------------------------
__global__ void prep_wcat_kernel(const float* __restrict__ W_off, const float* __restrict__ b_off,
                                 const float* __restrict__ W_attn, const float* __restrict__ b_attn)
{
    int i = blockIdx.x * blockDim.x + threadIdx.x;
    if (i < DMODEL * NPROJ) {
        int k = i / NPROJ, n = i % NPROJ;
        g_Wcat[i] = (n < 64) ? W_off[k * 64 + n] : W_attn[k * 32 + (n - 64)];
    }
    if (i < NPROJ) g_bcat[i] = (i < 64) ? b_off[i] : b_attn[i - 64];
}

// Transpose W_val and W_out (256x256 each) into g_WvalT / g_WoutT ([N,K]).
__global__ void transpose_w_kernel(const float* __restrict__ Wv, const float* __restrict__ Wo)
{
    __shared__ float t[32][33];
    const int which = blockIdx.x >> 6;
    const int bi = blockIdx.x & 63;
    const int tx = bi & 7, ty = bi >> 3;
    const float* W = which ? Wo : Wv;
    float* T = which ? g_WoutT : g_WvalT;
    int x = tx * 32 + threadIdx.x;
    int y = ty * 32 + threadIdx.y;
    #pragma unroll
    for (int i = 0; i < 32; i += 8)
        t[threadIdx.y + i][threadIdx.x] = W[(y + i) * DMODEL + x];
    __syncthreads();
    x = ty * 32 + threadIdx.x;
    y = tx * 32 + threadIdx.y;
    #pragma unroll
    for (int i = 0; i < 32; i += 8)
        T[(y + i) * DMODEL + x] = t[threadIdx.x][threadIdx.y + i];
}

// ---------------------------------------------------------------------------
// Prep table: coalesced smem staging of g_proj; thread = (bq_local, head).
// ---------------------------------------------------------------------------
__global__ __launch_bounds__(256) void prep_tab_kernel(
    const float* __restrict__ ref_pts,
    const int* __restrict__ hp, const int* __restrict__ wp)
{
    __shared__ float sproj[32 * NPROJ];
    __shared__ float sref[64];

    const int tid = threadIdx.x;
    const int bq0 = blockIdx.x * 32;

    #pragma unroll
    for (int j = 0; j < 12; j++)   // 32*96 = 3072 = 12*256
        sproj[tid + j * 256] = g_proj[(long)bq0 * NPROJ + tid + j * 256];
    if (tid < 64) sref[tid] = ref_pts[(long)bq0 * 2 + tid];
    __syncthreads();

    const int bql = tid >> 3;
    const int h = tid & 7;
    const int bq = bq0 + bql;
    const int b = bq / QLEN;
    const float* pr = sproj + bql * NPROJ;

    float l0 = pr[64 + h * 4 + 0], l1 = pr[64 + h * 4 + 1];
    float l2 = pr[64 + h * 4 + 2], l3 = pr[64 + h * 4 + 3];
    float m = fmaxf(fmaxf(l0, l1), fmaxf(l2, l3));
    float e0 = expf(l0 - m), e1 = expf(l1 - m), e2 = expf(l2 - m), e3 = expf(l3 - m);
    float inv = 1.f / (e0 + e1 + e2 + e3);
    float attn[NPOINTS] = { e0 * inv, e1 * inv, e2 * inv, e3 * inv };

    const int ww = *wp;
    const int hh = *hp;
    const float rx = sref[bql * 2 + 0];
    const float ry = sref[bql * 2 + 1];
    const int vbase = b * HWTOT * DMODEL + h * DHEAD;

    const long tslot = (long)bq * NHEADS + h;
    int* ti = g_tidx + tslot * 16;
    float* tw = g_tw + tslot * 16;

    #pragma unroll
    for (int p = 0; p < NPOINTS; p++) {
        const int hp4 = h * NPOINTS + p;
        float lx = fminf(fmaxf(rx + pr[hp4 * 2 + 0], 0.f), 1.f);
        float ly = fminf(fmaxf(ry + pr[hp4 * 2 + 1], 0.f), 1.f);
        float sx = lx * (float)(ww - 1);
        float sy = ly * (float)(hh - 1);
        int x0 = (int)floorf(sx); x0 = min(max(x0, 0), ww - 1);
        int y0 = (int)floorf(sy); y0 = min(max(y0, 0), hh - 1);
        int x1 = min(x0 + 1, ww - 1);
        int y1 = min(y0 + 1, hh - 1);
        float wx1 = sx - (float)x0, wx0 = 1.f - wx1;
        float wy1 = sy - (float)y0, wy0 = 1.f - wy1;
        float a = attn[p];
        ti[p * 4 + 0] = vbase + (y0 * ww + x0) * DMODEL;
        ti[p * 4 + 1] = vbase + (y1 * ww + x0) * DMODEL;
        ti[p * 4 + 2] = vbase + (y0 * ww + x1) * DMODEL;
        ti[p * 4 + 3] = vbase + (y1 * ww + x1) * DMODEL;
        tw[p * 4 + 0] = wx0 * wy0 * a;
        tw[p * 4 + 1] = wx0 * wy1 * a;
        tw[p * 4 + 2] = wx1 * wy0 * a;
        tw[p * 4 + 3] = wx1 * wy1 * a;
    }
}

// ---------------------------------------------------------------------------
// Gather: warp = (bq, head), lane = channel; 16 coalesced 128B gathers.
// ---------------------------------------------------------------------------
__global__ __launch_bounds__(256) void gather_kernel(float* __restrict__ sampled)
{
    const int wg = (blockIdx.x * blockDim.x + threadIdx.x) >> 5;
    const int lane = threadIdx.x & 31;
    if (wg >= BATCH * QLEN * NHEADS) return;

    const int4* ti = (const int4*)(g_tidx + (long)wg * 16);
    const float4* tw = (const float4*)(g_tw + (long)wg * 16);

    float acc = 0.f;
    #pragma unroll
    for (int c = 0; c < 4; c++) {
        int4 id = ti[c];
        float4 w = tw[c];
        acc = fmaf(w.x, g_values[id.x + lane], acc);
        acc = fmaf(w.y, g_values[id.y + lane], acc);
        acc = fmaf(w.z, g_values[id.z + lane], acc);
        acc = fmaf(w.w, g_values[id.w + lane], acc);
    }

    const int bq = wg >> 3;
    const int h = wg & 7;
    sampled[(long)bq * DMODEL + h * DHEAD + lane] = acc;
}

// ---------------------------------------------------------------------------
// Launch
// ---------------------------------------------------------------------------
extern "C" void kernel_launch(void* const* d_in, const int* in_sizes, int n_in,
                              void* d_out, int out_size)
{
    const float* query   = (const float*)d_in[0];
    const float* ref_pts = (const float*)d_in[1];
    const float* inp     = (const float*)d_in[2];
    const int*   hp      = (const int*)d_in[3];
    const int*   wp      = (const int*)d_in[4];
    const float* W_off   = (const float*)d_in[5];
    const float* b_off   = (const float*)d_in[6];
    const float* W_attn  = (const float*)d_in[7];
    const float* b_attn  = (const float*)d_in[8];
    const float* W_val   = (const float*)d_in[9];
    const float* b_val   = (const float*)d_in[10];
    const float* W_out   = (const float*)d_in[11];
    const float* b_out   = (const float*)d_in[12];
    float* out = (float*)d_out;

    float *values_ptr, *sampled_ptr, *proj_ptr, *wcat_ptr, *bcat_ptr, *wvt_ptr, *wot_ptr;
    cudaGetSymbolAddress((void**)&values_ptr, g_values);
    cudaGetSymbolAddress((void**)&sampled_ptr, g_sampled);
    cudaGetSymbolAddress((void**)&proj_ptr, g_proj);
    cudaGetSymbolAddress((void**)&wcat_ptr, g_Wcat);
    cudaGetSymbolAddress((void**)&bcat_ptr, g_bcat);
    cudaGetSymbolAddress((void**)&wvt_ptr, g_WvalT);
    cudaGetSymbolAddress((void**)&wot_ptr, g_WoutT);

    static bool attr_done = false;
    if (!attr_done) {
        cudaFuncSetAttribute(tf32_split_gemm_kernel,
                             cudaFuncAttributeMaxDynamicSharedMemorySize, GEMM_SMEM_BYTES);
        attr_done = true;
    }

    const int M1 = BATCH * HWTOT;   // 80000 = 625*128
    const int MQ = BATCH * QLEN;    // 16384 = 128*128

    // 0) weight prep
    prep_wcat_kernel<<<(DMODEL * NPROJ + 255) / 256, 256>>>(W_off, b_off, W_attn, b_attn);
    transpose_w_kernel<<<128, dim3(32, 8)>>>(W_val, W_out);

    // 1) values = input_flatten @ W_val + b_val   (fp16 mma, fp32 accum)
    {
        dim3 grid(DMODEL / HBN_, M1 / HBM_);
        fp16_gemm_kernel<<<grid, 256>>>(inp, wvt_ptr, b_val, values_ptr,
                                        M1, DMODEL, DMODEL);
    }

    // 2) proj = query @ [W_off|W_attn] + bias   (3xTF32: precision-critical)
    {
        dim3 grid(1, MQ / GBM);
        tf32_split_gemm_kernel<<<grid, 256, GEMM_SMEM_BYTES>>>(
            query, wcat_ptr, bcat_ptr, proj_ptr, MQ, NPROJ, DMODEL);
    }

    // 3a) softmax + bilinear table (coalesced)
    prep_tab_kernel<<<MQ / 32, 256>>>(ref_pts, hp, wp);

    // 3b) gather
    gather_kernel<<<(MQ * NHEADS) / 8, 256>>>(sampled_ptr);

    // 4) out = sampled @ W_out + b_out   (fp16 mma, fp32 accum)
    {
        dim3 grid(DMODEL / HBN_, MQ / HBM_);
        fp16_gemm_kernel<<<grid, 256>>>(sampled_ptr, wot_ptr, b_out, out,
                                        MQ, DMODEL, DMODEL);
    }
}

// round 6
// speedup vs baseline: 2.6518x; 1.0821x over previous
#include <cuda_runtime.h>
#include <cuda_fp16.h>
#include <math.h>
#include <stdint.h>

// Problem constants (fixed by the dataset instance)
#define NHEADS 8
#define NPOINTS 4
#define DMODEL 256
#define DHEAD 32
#define BATCH 8
#define QLEN 2048
#define HWTOT 10000
#define NPROJ 96   // 64 offset cols + 32 attn cols

// Scratch (device globals — no allocation allowed)
__device__ float g_values[(size_t)BATCH * HWTOT * DMODEL];
__device__ float g_sampled[(size_t)BATCH * QLEN * DMODEL];
__device__ float g_proj[(size_t)BATCH * QLEN * NPROJ];
__device__ float g_Wcat[DMODEL * NPROJ];
__device__ float g_bcat[NPROJ];
__device__ float g_WvalT[DMODEL * DMODEL];
__device__ float g_WoutT[DMODEL * DMODEL];
__device__ int   g_tidx[(size_t)BATCH * QLEN * NHEADS * 16];
__device__ float g_tw[(size_t)BATCH * QLEN * NHEADS * 16];

// ---------------------------------------------------------------------------
// helpers
// ---------------------------------------------------------------------------
__device__ __forceinline__ uint32_t f2tf32(float x) {
    uint32_t u;
    asm("cvt.rna.tf32.f32 %0, %1;" : "=r"(u) : "f"(x));
    return u;
}
__device__ __forceinline__ float tf32f(float x) {
    return __uint_as_float(f2tf32(x));
}
__device__ __forceinline__ uint32_t packh2(float x, float y) {
    __half2 h = __floats2half2_rn(x, y);
    return *(uint32_t*)&h;
}

__device__ __forceinline__ void mma16816(float d[4],
                                         uint32_t a0, uint32_t a1, uint32_t a2, uint32_t a3,
                                         uint32_t b0, uint32_t b1) {
    asm volatile(
        "mma.sync.aligned.m16n8k16.row.col.f32.f16.f16.f32 "
        "{%0,%1,%2,%3}, {%4,%5,%6,%7}, {%8,%9}, {%0,%1,%2,%3};"
        : "+f"(d[0]), "+f"(d[1]), "+f"(d[2]), "+f"(d[3])
        : "r"(a0), "r"(a1), "r"(a2), "r"(a3), "r"(b0), "r"(b1));
}
__device__ __forceinline__ void mma8(float d[4],
                                     uint32_t a0, uint32_t a1, uint32_t a2, uint32_t a3,
                                     uint32_t b0, uint32_t b1) {
    asm volatile(
        "mma.sync.aligned.m16n8k8.row.col.f32.tf32.tf32.f32 "
        "{%0,%1,%2,%3}, {%4,%5,%6,%7}, {%8,%9}, {%0,%1,%2,%3};"
        : "+f"(d[0]), "+f"(d[1]), "+f"(d[2]), "+f"(d[3])
        : "r"(a0), "r"(a1), "r"(a2), "r"(a3), "r"(b0), "r"(b1));
}
__device__ __forceinline__ void cpasync16(uint32_t smem_addr, const void* gptr) {
    asm volatile("cp.async.cg.shared.global [%0], [%1], 16;\n"
                 :: "r"(smem_addr), "l"(gptr));
}
__device__ __forceinline__ void cpasync16p(uint32_t smem_addr, const void* gptr, bool valid) {
    int sz = valid ? 16 : 0;
    asm volatile("cp.async.cg.shared.global [%0], [%1], 16, %2;\n"
                 :: "r"(smem_addr), "l"(gptr), "r"(sz));
}
__device__ __forceinline__ void cpasync_commit() {
    asm volatile("cp.async.commit_group;\n" ::);
}
template<int Ncp>
__device__ __forceinline__ void cpasync_wait() {
    asm volatile("cp.async.wait_group %0;\n" :: "n"(Ncp));
}

// ---------------------------------------------------------------------------
// FP16 tensor-core GEMM, cp.async pipelined (fp32 staged; cvt at fragment read).
// C[M,N] = A[M,K] @ BT^T + bias  (BT is [N,K] row-major; all fp32 in gmem).
// Block tile 128x128x32, 256 threads (8 warps 4x2), warp tile 32x64.
// Requires M%128==0, N%128==0, K%32==0.
// ---------------------------------------------------------------------------
#define FBM 128
#define FBN 128
#define FBK 32
#define FSTAGES 3
#define FSTR 36   // floats per row (32 + 4 pad)
#define FP16_SMEM_BYTES (FSTAGES * 2 * FBM * FSTR * 4)   // 110,592 B

__global__ __launch_bounds__(256) void fp16_gemm_kernel(
    const float* __restrict__ A, const float* __restrict__ BT,
    const float* __restrict__ bias, float* __restrict__ C,
    int M, int N, int K)
{
    extern __shared__ __align__(16) float fsm[];
    float* As = fsm;                              // [FSTAGES][FBM][FSTR]
    float* Bs = fsm + FSTAGES * FBM * FSTR;       // [FSTAGES][FBN][FSTR]

    const int t = threadIdx.x;
    const int warp = t >> 5;
    const int lane = t & 31;
    const int g = lane >> 2;
    const int tig = lane & 3;
    const int wm = (warp >> 1) * 32;
    const int wn = (warp & 1) * 64;

    const int rowTile = blockIdx.y * FBM;
    const int colTile = blockIdx.x * FBN;
    const float* Ag = A + (long)rowTile * K;
    const float* Bg = BT + (long)colTile * K;

    // loader: tile = 128 rows x 8 float4; 1024 float4 / 256 thr = 4 each
    const int lr = t >> 1;                 // rows: two threads per row
    const int lc = (t & 1) * 4;            // float4 col {0,4}
    // each thread: rows lr, lr+... wait: 128 rows x 8 float4 = 1024; per thread 4.
    // mapping: idx = t + j*256 -> r = idx>>3, fc = idx&7
    uint32_t sAaddr[4], sBaddr[4];
    const float* gA[4];
    const float* gB[4];
    #pragma unroll
    for (int j = 0; j < 4; j++) {
        const int idx = t + j * 256;
        const int r = idx >> 3;
        const int fc = idx & 7;
        sAaddr[j] = (uint32_t)__cvta_generic_to_shared(As + r * FSTR + fc * 4);
        sBaddr[j] = (uint32_t)__cvta_generic_to_shared(Bs + r * FSTR + fc * 4);
        gA[j] = Ag + (long)r * K + fc * 4;
        gB[j] = Bg + (long)r * K + fc * 4;
    }
    const uint32_t stageB = FBM * FSTR * 4;
    const int kIters = K / FBK;

    auto issue_tile = [&](int tile) {
        if (tile < kIters) {
            const int s = tile % FSTAGES;
            const int k0 = tile * FBK;
            #pragma unroll
            for (int j = 0; j < 4; j++) {
                cpasync16(sAaddr[j] + s * stageB, gA[j] + k0);
                cpasync16(sBaddr[j] + s * stageB, gB[j] + k0);
            }
        }
        cpasync_commit();
    };

    float acc[2][8][4];
    #pragma unroll
    for (int i = 0; i < 2; i++)
        #pragma unroll
        for (int j = 0; j < 8; j++)
            #pragma unroll
            for (int r = 0; r < 4; r++) acc[i][j][r] = 0.f;

    #pragma unroll
    for (int s = 0; s < FSTAGES - 1; s++) issue_tile(s);

    #pragma unroll 1
    for (int it = 0; it < kIters; ++it) {
        cpasync_wait<FSTAGES - 2>();
        __syncthreads();
        issue_tile(it + FSTAGES - 1);

        const int s = it % FSTAGES;
        const float* AsS = As + s * FBM * FSTR;
        const float* BsS = Bs + s * FBN * FSTR;

        #pragma unroll
        for (int ks = 0; ks < 2; ks++) {     // two k16 steps
            const int kb = ks * 16 + 2 * tig;
            uint32_t af[2][4];
            #pragma unroll
            for (int mt = 0; mt < 2; mt++) {
                const int m0 = wm + mt * 16;
                float2 v0 = *(const float2*)&AsS[(m0 + g) * FSTR + kb];
                float2 v1 = *(const float2*)&AsS[(m0 + g + 8) * FSTR + kb];
                float2 v2 = *(const float2*)&AsS[(m0 + g) * FSTR + kb + 8];
                float2 v3 = *(const float2*)&AsS[(m0 + g + 8) * FSTR + kb + 8];
                af[mt][0] = packh2(v0.x, v0.y);
                af[mt][1] = packh2(v1.x, v1.y);
                af[mt][2] = packh2(v2.x, v2.y);
                af[mt][3] = packh2(v3.x, v3.y);
            }
            uint32_t bf[8][2];
            #pragma unroll
            for (int nt = 0; nt < 8; nt++) {
                const int n0 = wn + nt * 8;
                float2 u0 = *(const float2*)&BsS[(n0 + g) * FSTR + kb];
                float2 u1 = *(const float2*)&BsS[(n0 + g) * FSTR + kb + 8];
                bf[nt][0] = packh2(u0.x, u0.y);
                bf[nt][1] = packh2(u1.x, u1.y);
            }
            #pragma unroll
            for (int mt = 0; mt < 2; mt++)
                #pragma unroll
                for (int nt = 0; nt < 8; nt++)
                    mma16816(acc[mt][nt], af[mt][0], af[mt][1], af[mt][2], af[mt][3],
                             bf[nt][0], bf[nt][1]);
        }
        __syncthreads();
    }

    // epilogue
    #pragma unroll
    for (int mt = 0; mt < 2; mt++) {
        #pragma unroll
        for (int nt = 0; nt < 8; nt++) {
            const int c = colTile + wn + nt * 8 + tig * 2;
            const float b0 = bias[c], b1 = bias[c + 1];
            const int r0 = rowTile + wm + mt * 16 + g;
            float2 v0 = make_float2(acc[mt][nt][0] + b0, acc[mt][nt][1] + b1);
            *(float2*)(C + (long)r0 * N + c) = v0;
            float2 v1 = make_float2(acc[mt][nt][2] + b0, acc[mt][nt][3] + b1);
            *(float2*)(C + (long)(r0 + 8) * N + c) = v1;
        }
    }
}

// ---------------------------------------------------------------------------
// mma.sync 3xTF32 split GEMM (precision-critical offset/attn projection only).
// ---------------------------------------------------------------------------
#define GBM 128
#define GBN 128
#define GBK 16
#define STAGES 4
#define AS_STRIDE 20
#define BS_STRIDE 132
#define GEMM_SMEM_BYTES (STAGES * (GBM * AS_STRIDE + GBK * BS_STRIDE) * 4)

__global__ __launch_bounds__(256) void tf32_split_gemm_kernel(
    const float* __restrict__ A, const float* __restrict__ B,
    const float* __restrict__ bias, float* __restrict__ C,
    int M, int N, int K)
{
    extern __shared__ __align__(16) float dsmf[];
    float* As = dsmf;
    float* Bs = dsmf + STAGES * GBM * AS_STRIDE;

    const int t = threadIdx.x;
    const int warp = t >> 5;
    const int lane = t & 31;
    const int g = lane >> 2;
    const int tig = lane & 3;
    const int wm = (warp >> 1) * 32;
    const int wn = (warp & 1) * 64;

    const int rowTile = blockIdx.y * GBM;
    const int colTile = blockIdx.x * GBN;

    const int ar0 = t >> 2;
    const int ar1 = ar0 + 64;
    const int ac = (t & 3) * 4;
    const int bk0 = t >> 5;
    const int bk1 = bk0 + 8;
    const int bc = (t & 31) * 4;

    const bool aok0 = (rowTile + ar0) < M;
    const bool aok1 = (rowTile + ar1) < M;
    const bool bok = (colTile + bc) < N;

    const float* Ap0 = A + (long)(rowTile + ar0) * K + ac;
    const float* Ap1 = A + (long)(rowTile + ar1) * K + ac;
    const float* Bp0 = B + (long)bk0 * N + colTile + bc;
    const float* Bp1 = B + (long)bk1 * N + colTile + bc;

    const uint32_t aStageB = GBM * AS_STRIDE * 4;
    const uint32_t bStageB = GBK * BS_STRIDE * 4;
    const uint32_t sA0 = (uint32_t)__cvta_generic_to_shared(As + ar0 * AS_STRIDE + ac);
    const uint32_t sA1 = (uint32_t)__cvta_generic_to_shared(As + ar1 * AS_STRIDE + ac);
    const uint32_t sB0 = (uint32_t)__cvta_generic_to_shared(Bs + bk0 * BS_STRIDE + bc);
    const uint32_t sB1 = (uint32_t)__cvta_generic_to_shared(Bs + bk1 * BS_STRIDE + bc);

    const int kIters = K / GBK;

    auto issue_tile = [&](int tile) {
        if (tile < kIters) {
            const int s = tile % STAGES;
            const long k0 = (long)tile * GBK;
            cpasync16p(sA0 + s * aStageB, Ap0 + k0, aok0);
            cpasync16p(sA1 + s * aStageB, Ap1 + k0, aok1);
            cpasync16p(sB0 + s * bStageB, Bp0 + k0 * N, bok);
            cpasync16p(sB1 + s * bStageB, Bp1 + k0 * N, bok);
        }
        cpasync_commit();
    };

    float acc[2][8][4];
    #pragma unroll
    for (int i = 0; i < 2; i++)
        #pragma unroll
        for (int j = 0; j < 8; j++)
            #pragma unroll
            for (int r = 0; r < 4; r++) acc[i][j][r] = 0.f;

    #pragma unroll
    for (int s = 0; s < STAGES - 1; s++) issue_tile(s);

    #pragma unroll 1
    for (int it = 0; it < kIters; ++it) {
        cpasync_wait<STAGES - 2>();
        __syncthreads();
        issue_tile(it + STAGES - 1);

        const int s = it % STAGES;
        const float* AsS = As + s * GBM * AS_STRIDE;
        const float* BsS = Bs + s * GBK * BS_STRIDE;

        #pragma unroll
        for (int kk = 0; kk < GBK; kk += 8) {
            float ar[2][4];
            #pragma unroll
            for (int mt = 0; mt < 2; mt++) {
                const int m0 = wm + mt * 16;
                ar[mt][0] = AsS[(m0 + g) * AS_STRIDE + kk + tig];
                ar[mt][1] = AsS[(m0 + g + 8) * AS_STRIDE + kk + tig];
                ar[mt][2] = AsS[(m0 + g) * AS_STRIDE + kk + tig + 4];
                ar[mt][3] = AsS[(m0 + g + 8) * AS_STRIDE + kk + tig + 4];
            }
            float br[8][2];
            #pragma unroll
            for (int nt = 0; nt < 8; nt++) {
                br[nt][0] = BsS[(kk + tig) * BS_STRIDE + wn + nt * 8 + g];
                br[nt][1] = BsS[(kk + tig + 4) * BS_STRIDE + wn + nt * 8 + g];
            }
            uint32_t ahi[2][4], alo[2][4];
            #pragma unroll
            for (int mt = 0; mt < 2; mt++)
                #pragma unroll
                for (int r = 0; r < 4; r++) {
                    float hi = tf32f(ar[mt][r]);
                    ahi[mt][r] = __float_as_uint(hi);
                    alo[mt][r] = f2tf32(ar[mt][r] - hi);
                }
            uint32_t bhi[8][2], blo[8][2];
            #pragma unroll
            for (int nt = 0; nt < 8; nt++)
                #pragma unroll
                for (int r = 0; r < 2; r++) {
                    float hi = tf32f(br[nt][r]);
                    bhi[nt][r] = __float_as_uint(hi);
                    blo[nt][r] = f2tf32(br[nt][r] - hi);
                }
            #pragma unroll
            for (int mt = 0; mt < 2; mt++)
                #pragma unroll
                for (int nt = 0; nt < 8; nt++) {
                    mma8(acc[mt][nt], ahi[mt][0], ahi[mt][1], ahi[mt][2], ahi[mt][3],
                         blo[nt][0], blo[nt][1]);
                    mma8(acc[mt][nt], alo[mt][0], alo[mt][1], alo[mt][2], alo[mt][3],
                         bhi[nt][0], bhi[nt][1]);
                    mma8(acc[mt][nt], ahi[mt][0], ahi[mt][1], ahi[mt][2], ahi[mt][3],
                         bhi[nt][0], bhi[nt][1]);
                }
        }
    }

    #pragma unroll
    for (int mt = 0; mt < 2; mt++) {
        #pragma unroll
        for (int nt = 0; nt < 8; nt++) {
            const int c = colTile + wn + nt * 8 + tig * 2;
            if (c >= N) continue;
            const float b0 = bias[c], b1 = bias[c + 1];
            const int r0 = rowTile + wm + mt * 16 + g;
            if (r0 < M) {
                float2 v = make_float2(acc[mt][nt][0] + b0, acc[mt][nt][1] + b1);
                *(float2*)(C + (long)r0 * N + c) = v;
            }
            const int r1 = r0 + 8;
            if (r1 < M) {
                float2 v = make_float2(acc[mt][nt][2] + b0, acc[mt][nt][3] + b1);
                *(float2*)(C + (long)r1 * N + c) = v;
            }
        }
    }
}

// ---------------------------------------------------------------------------
// Prep kernels
// ---------------------------------------------------------------------------
__global__ void prep_wcat_kernel(const float* __restrict__ W_off, const float* __restrict__ b_off,
                                 const float* __restrict__ W_attn, const float* __restrict__ b_attn)
{
    int i = blockIdx.x * blockDim.x + threadIdx.x;
    if (i < DMODEL * NPROJ) {
        int k = i / NPROJ, n = i % NPROJ;
        g_Wcat[i] = (n < 64) ? W_off[k * 64 + n] : W_attn[k * 32 + (n - 64)];
    }
    if (i < NPROJ) g_bcat[i] = (i < 64) ? b_off[i] : b_attn[i - 64];
}

__global__ void transpose_w_kernel(const float* __restrict__ Wv, const float* __restrict__ Wo)
{
    __shared__ float t[32][33];
    const int which = blockIdx.x >> 6;
    const int bi = blockIdx.x & 63;
    const int tx = bi & 7, ty = bi >> 3;
    const float* W = which ? Wo : Wv;
    float* T = which ? g_WoutT : g_WvalT;
    int x = tx * 32 + threadIdx.x;
    int y = ty * 32 + threadIdx.y;
    #pragma unroll
    for (int i = 0; i < 32; i += 8)
        t[threadIdx.y + i][threadIdx.x] = W[(y + i) * DMODEL + x];
    __syncthreads();
    x = ty * 32 + threadIdx.x;
    y = tx * 32 + threadIdx.y;
    #pragma unroll
    for (int i = 0; i < 32; i += 8)
        T[(y + i) * DMODEL + x] = t[threadIdx.x][threadIdx.y + i];
}

// ---------------------------------------------------------------------------
// Prep table: coalesced smem staging of g_proj; thread = (bq_local, head).
// ---------------------------------------------------------------------------
__global__ __launch_bounds__(256) void prep_tab_kernel(
    const float* __restrict__ ref_pts,
    const int* __restrict__ hp, const int* __restrict__ wp)
{
    __shared__ float sproj[32 * NPROJ];
    __shared__ float sref[64];

    const int tid = threadIdx.x;
    const int bq0 = blockIdx.x * 32;

    #pragma unroll
    for (int j = 0; j < 12; j++)
        sproj[tid + j * 256] = g_proj[(long)bq0 * NPROJ + tid + j * 256];
    if (tid < 64) sref[tid] = ref_pts[(long)bq0 * 2 + tid];
    __syncthreads();

    const int bql = tid >> 3;
    const int h = tid & 7;
    const int bq = bq0 + bql;
    const int b = bq / QLEN;
    const float* pr = sproj + bql * NPROJ;

    float l0 = pr[64 + h * 4 + 0], l1 = pr[64 + h * 4 + 1];
    float l2 = pr[64 + h * 4 + 2], l3 = pr[64 + h * 4 + 3];
    float m = fmaxf(fmaxf(l0, l1), fmaxf(l2, l3));
    float e0 = expf(l0 - m), e1 = expf(l1 - m), e2 = expf(l2 - m), e3 = expf(l3 - m);
    float inv = 1.f / (e0 + e1 + e2 + e3);
    float attn[NPOINTS] = { e0 * inv, e1 * inv, e2 * inv, e3 * inv };

    const int ww = *wp;
    const int hh = *hp;
    const float rx = sref[bql * 2 + 0];
    const float ry = sref[bql * 2 + 1];
    const int vbase = b * HWTOT * DMODEL + h * DHEAD;

    const long tslot = (long)bq * NHEADS + h;
    int* ti = g_tidx + tslot * 16;
    float* tw = g_tw + tslot * 16;

    #pragma unroll
    for (int p = 0; p < NPOINTS; p++) {
        const int hp4 = h * NPOINTS + p;
        float lx = fminf(fmaxf(rx + pr[hp4 * 2 + 0], 0.f), 1.f);
        float ly = fminf(fmaxf(ry + pr[hp4 * 2 + 1], 0.f), 1.f);
        float sx = lx * (float)(ww - 1);
        float sy = ly * (float)(hh - 1);
        int x0 = (int)floorf(sx); x0 = min(max(x0, 0), ww - 1);
        int y0 = (int)floorf(sy); y0 = min(max(y0, 0), hh - 1);
        int x1 = min(x0 + 1, ww - 1);
        int y1 = min(y0 + 1, hh - 1);
        float wx1 = sx - (float)x0, wx0 = 1.f - wx1;
        float wy1 = sy - (float)y0, wy0 = 1.f - wy1;
        float a = attn[p];
        ti[p * 4 + 0] = vbase + (y0 * ww + x0) * DMODEL;
        ti[p * 4 + 1] = vbase + (y1 * ww + x0) * DMODEL;
        ti[p * 4 + 2] = vbase + (y0 * ww + x1) * DMODEL;
        ti[p * 4 + 3] = vbase + (y1 * ww + x1) * DMODEL;
        tw[p * 4 + 0] = wx0 * wy0 * a;
        tw[p * 4 + 1] = wx0 * wy1 * a;
        tw[p * 4 + 2] = wx1 * wy0 * a;
        tw[p * 4 + 3] = wx1 * wy1 * a;
    }
}

// ---------------------------------------------------------------------------
// Gather: warp = (bq, head), lane = channel; 16 coalesced 128B gathers.
// ---------------------------------------------------------------------------
__global__ __launch_bounds__(256) void gather_kernel(float* __restrict__ sampled)
{
    const int wg = (blockIdx.x * blockDim.x + threadIdx.x) >> 5;
    const int lane = threadIdx.x & 31;
    if (wg >= BATCH * QLEN * NHEADS) return;

    const int4* ti = (const int4*)(g_tidx + (long)wg * 16);
    const float4* tw = (const float4*)(g_tw + (long)wg * 16);

    float acc = 0.f;
    #pragma unroll
    for (int c = 0; c < 4; c++) {
        int4 id = ti[c];
        float4 w = tw[c];
        acc = fmaf(w.x, g_values[id.x + lane], acc);
        acc = fmaf(w.y, g_values[id.y + lane], acc);
        acc = fmaf(w.z, g_values[id.z + lane], acc);
        acc = fmaf(w.w, g_values[id.w + lane], acc);
    }

    const int bq = wg >> 3;
    const int h = wg & 7;
    sampled[(long)bq * DMODEL + h * DHEAD + lane] = acc;
}

// ---------------------------------------------------------------------------
// Launch — two streams: s0 (value GEMM path) || s1 (proj path), join at gather.
// ---------------------------------------------------------------------------
extern "C" void kernel_launch(void* const* d_in, const int* in_sizes, int n_in,
                              void* d_out, int out_size)
{
    const float* query   = (const float*)d_in[0];
    const float* ref_pts = (const float*)d_in[1];
    const float* inp     = (const float*)d_in[2];
    const int*   hp      = (const int*)d_in[3];
    const int*   wp      = (const int*)d_in[4];
    const float* W_off   = (const float*)d_in[5];
    const float* b_off   = (const float*)d_in[6];
    const float* W_attn  = (const float*)d_in[7];
    const float* b_attn  = (const float*)d_in[8];
    const float* W_val   = (const float*)d_in[9];
    const float* b_val   = (const float*)d_in[10];
    const float* W_out   = (const float*)d_in[11];
    const float* b_out   = (const float*)d_in[12];
    float* out = (float*)d_out;

    float *values_ptr, *sampled_ptr, *proj_ptr, *wcat_ptr, *bcat_ptr, *wvt_ptr, *wot_ptr;
    cudaGetSymbolAddress((void**)&values_ptr, g_values);
    cudaGetSymbolAddress((void**)&sampled_ptr, g_sampled);
    cudaGetSymbolAddress((void**)&proj_ptr, g_proj);
    cudaGetSymbolAddress((void**)&wcat_ptr, g_Wcat);
    cudaGetSymbolAddress((void**)&bcat_ptr, g_bcat);
    cudaGetSymbolAddress((void**)&wvt_ptr, g_WvalT);
    cudaGetSymbolAddress((void**)&wot_ptr, g_WoutT);

    static cudaStream_t s1 = nullptr;
    static cudaEvent_t evFork = nullptr, evJoin = nullptr;
    if (!s1) {
        cudaStreamCreateWithFlags(&s1, cudaStreamNonBlocking);
        cudaEventCreateWithFlags(&evFork, cudaEventDisableTiming);
        cudaEventCreateWithFlags(&evJoin, cudaEventDisableTiming);
        cudaFuncSetAttribute(tf32_split_gemm_kernel,
                             cudaFuncAttributeMaxDynamicSharedMemorySize, GEMM_SMEM_BYTES);
        cudaFuncSetAttribute(fp16_gemm_kernel,
                             cudaFuncAttributeMaxDynamicSharedMemorySize, FP16_SMEM_BYTES);
    }

    const int M1 = BATCH * HWTOT;   // 80000
    const int MQ = BATCH * QLEN;    // 16384

    // ---- fork: s1 runs the (independent) projection path
    cudaEventRecord(evFork, 0);
    cudaStreamWaitEvent(s1, evFork, 0);

    // s1: concat weights -> proj GEMM -> softmax/bilinear table
    prep_wcat_kernel<<<(DMODEL * NPROJ + 255) / 256, 256, 0, s1>>>(
        W_off, b_off, W_attn, b_attn);
    {
        dim3 grid(1, MQ / GBM);
        tf32_split_gemm_kernel<<<grid, 256, GEMM_SMEM_BYTES, s1>>>(
            query, wcat_ptr, bcat_ptr, proj_ptr, MQ, NPROJ, DMODEL);
    }
    prep_tab_kernel<<<MQ / 32, 256, 0, s1>>>(ref_pts, hp, wp);
    cudaEventRecord(evJoin, s1);

    // stream 0: transpose weights, then the big value GEMM
    transpose_w_kernel<<<128, dim3(32, 8)>>>(W_val, W_out);
    {
        dim3 grid(DMODEL / FBN, M1 / FBM);
        fp16_gemm_kernel<<<grid, 256, FP16_SMEM_BYTES>>>(
            inp, wvt_ptr, b_val, values_ptr, M1, DMODEL, DMODEL);
    }

    // ---- join: gather needs values (s0) + table (s1)
    cudaStreamWaitEvent(0, evJoin, 0);
    gather_kernel<<<(MQ * NHEADS) / 8, 256>>>(sampled_ptr);

    // out = sampled @ W_out + b_out
    {
        dim3 grid(DMODEL / FBN, MQ / FBM);
        fp16_gemm_kernel<<<grid, 256, FP16_SMEM_BYTES>>>(
            sampled_ptr, wot_ptr, b_out, out, MQ, DMODEL, DMODEL);
    }
}

// round 7
// speedup vs baseline: 2.7710x; 1.0449x over previous
#include <cuda_runtime.h>
#include <cuda_fp16.h>
#include <math.h>
#include <stdint.h>

// Problem constants (fixed by the dataset instance)
#define NHEADS 8
#define NPOINTS 4
#define DMODEL 256
#define DHEAD 32
#define BATCH 8
#define QLEN 2048
#define HWTOT 10000
#define NPROJ 96   // 64 offset cols + 32 attn cols

// Scratch (device globals — no allocation allowed)
__device__ __half g_valh[(size_t)BATCH * HWTOT * DMODEL];    // 40.96 MB
__device__ __half g_samph[(size_t)BATCH * QLEN * DMODEL];    //  8.39 MB
__device__ float  g_proj[(size_t)BATCH * QLEN * NPROJ];
__device__ float  g_Wcat[DMODEL * NPROJ];
__device__ float  g_bcat[NPROJ];
__device__ __half g_WvalTh[DMODEL * DMODEL];                 // [N][K] half
__device__ __half g_WoutTh[DMODEL * DMODEL];
__device__ int    g_tidx[(size_t)BATCH * QLEN * NHEADS * 16];
__device__ float  g_tw[(size_t)BATCH * QLEN * NHEADS * 16];

// ---------------------------------------------------------------------------
// helpers
// ---------------------------------------------------------------------------
__device__ __forceinline__ uint32_t f2tf32(float x) {
    uint32_t u;
    asm("cvt.rna.tf32.f32 %0, %1;" : "=r"(u) : "f"(x));
    return u;
}
__device__ __forceinline__ float tf32f(float x) {
    return __uint_as_float(f2tf32(x));
}
__device__ __forceinline__ uint32_t packh2(float x, float y) {
    __half2 h = __floats2half2_rn(x, y);
    return *(uint32_t*)&h;
}

__device__ __forceinline__ void mma16816(float d[4],
                                         uint32_t a0, uint32_t a1, uint32_t a2, uint32_t a3,
                                         uint32_t b0, uint32_t b1) {
    asm volatile(
        "mma.sync.aligned.m16n8k16.row.col.f32.f16.f16.f32 "
        "{%0,%1,%2,%3}, {%4,%5,%6,%7}, {%8,%9}, {%0,%1,%2,%3};"
        : "+f"(d[0]), "+f"(d[1]), "+f"(d[2]), "+f"(d[3])
        : "r"(a0), "r"(a1), "r"(a2), "r"(a3), "r"(b0), "r"(b1));
}
__device__ __forceinline__ void mma8(float d[4],
                                     uint32_t a0, uint32_t a1, uint32_t a2, uint32_t a3,
                                     uint32_t b0, uint32_t b1) {
    asm volatile(
        "mma.sync.aligned.m16n8k8.row.col.f32.tf32.tf32.f32 "
        "{%0,%1,%2,%3}, {%4,%5,%6,%7}, {%8,%9}, {%0,%1,%2,%3};"
        : "+f"(d[0]), "+f"(d[1]), "+f"(d[2]), "+f"(d[3])
        : "r"(a0), "r"(a1), "r"(a2), "r"(a3), "r"(b0), "r"(b1));
}
__device__ __forceinline__ void cpasync16(uint32_t smem_addr, const void* gptr) {
    asm volatile("cp.async.cg.shared.global [%0], [%1], 16;\n"
                 :: "r"(smem_addr), "l"(gptr));
}
__device__ __forceinline__ void cpasync16p(uint32_t smem_addr, const void* gptr, bool valid) {
    int sz = valid ? 16 : 0;
    asm volatile("cp.async.cg.shared.global [%0], [%1], 16, %2;\n"
                 :: "r"(smem_addr), "l"(gptr), "r"(sz));
}
__device__ __forceinline__ void cpasync_commit() {
    asm volatile("cp.async.commit_group;\n" ::);
}
template<int Ncp>
__device__ __forceinline__ void cpasync_wait() {
    asm volatile("cp.async.wait_group %0;\n" :: "n"(Ncp));
}

// ---------------------------------------------------------------------------
// FP16 tensor-core GEMM, cp.async 3-stage pipeline.
//   AH = A is half in gmem (else fp32, converted at fragment read)
//   CH = C stored as half (else fp32)
// C[M,N] = A[M,K] @ BT^T + bias  (BT is half [N,K] row-major)
// Block tile 128x128x32, 256 threads (8 warps 4x2), warp tile 32x64.
// Requires M%128==0, N%128==0, K%32==0.
// ---------------------------------------------------------------------------
#define FBM 128
#define FBN 128
#define FBK 32
#define FSTAGES 3
#define FSTRF 36   // floats per A row (fp32 variant)
#define FSTRH 40   // halfs per row (half variant / B)

template<bool AH, bool CH>
__global__ __launch_bounds__(256) void fp16_gemm_kernel(
    const void* __restrict__ Av, const __half* __restrict__ BT,
    const float* __restrict__ bias, void* __restrict__ Cv,
    int M, int N, int K)
{
    extern __shared__ __align__(16) char fsm[];
    const int aStageBytes = AH ? (FBM * FSTRH * 2) : (FBM * FSTRF * 4);
    const int bStageBytes = FBN * FSTRH * 2;
    char* Abase = fsm;
    char* Bbase = fsm + FSTAGES * aStageBytes;

    const int t = threadIdx.x;
    const int warp = t >> 5;
    const int lane = t & 31;
    const int g = lane >> 2;
    const int tig = lane & 3;
    const int wm = (warp >> 1) * 32;
    const int wn = (warp & 1) * 64;

    const int rowTile = blockIdx.y * FBM;
    const int colTile = blockIdx.x * FBN;
    const __half* Bg = BT + (long)colTile * K;

    // ---- loader setup
    uint32_t sAaddr[4], sBaddr[2];
    const char* gA[4];
    const __half* gB[2];
    if (AH) {
        const __half* Ag = (const __half*)Av + (long)rowTile * K;
        #pragma unroll
        for (int j = 0; j < 2; j++) {   // 128 rows x 32 halfs = 512 x 16B chunks/... 512/256=2
            const int idx = t + j * 256;
            const int r = idx >> 2;
            const int hc = (idx & 3) * 8;
            sAaddr[j] = (uint32_t)__cvta_generic_to_shared(Abase + (r * FSTRH + hc) * 2);
            gA[j] = (const char*)(Ag + (long)r * K + hc);
        }
    } else {
        const float* Ag = (const float*)Av + (long)rowTile * K;
        #pragma unroll
        for (int j = 0; j < 4; j++) {   // 128 rows x 8 float4 = 1024 chunks / 256 = 4
            const int idx = t + j * 256;
            const int r = idx >> 3;
            const int fc = idx & 7;
            sAaddr[j] = (uint32_t)__cvta_generic_to_shared(Abase + (r * FSTRF + fc * 4) * 4);
            gA[j] = (const char*)(Ag + (long)r * K + fc * 4);
        }
    }
    #pragma unroll
    for (int j = 0; j < 2; j++) {
        const int idx = t + j * 256;
        const int r = idx >> 2;
        const int hc = (idx & 3) * 8;
        sBaddr[j] = (uint32_t)__cvta_generic_to_shared(Bbase + (r * FSTRH + hc) * 2);
        gB[j] = Bg + (long)r * K + hc;
    }

    const int kIters = K / FBK;
    auto issue_tile = [&](int tile) {
        if (tile < kIters) {
            const int s = tile % FSTAGES;
            const int k0 = tile * FBK;
            if (AH) {
                #pragma unroll
                for (int j = 0; j < 2; j++)
                    cpasync16(sAaddr[j] + s * aStageBytes, gA[j] + (long)k0 * 2);
            } else {
                #pragma unroll
                for (int j = 0; j < 4; j++)
                    cpasync16(sAaddr[j] + s * aStageBytes, gA[j] + (long)k0 * 4);
            }
            #pragma unroll
            for (int j = 0; j < 2; j++)
                cpasync16(sBaddr[j] + s * bStageBytes, gB[j] + k0);
        }
        cpasync_commit();
    };

    float acc[2][8][4];
    #pragma unroll
    for (int i = 0; i < 2; i++)
        #pragma unroll
        for (int j = 0; j < 8; j++)
            #pragma unroll
            for (int r = 0; r < 4; r++) acc[i][j][r] = 0.f;

    #pragma unroll
    for (int s = 0; s < FSTAGES - 1; s++) issue_tile(s);

    #pragma unroll 1
    for (int it = 0; it < kIters; ++it) {
        cpasync_wait<FSTAGES - 2>();
        __syncthreads();
        issue_tile(it + FSTAGES - 1);

        const int s = it % FSTAGES;
        const __half* BsS = (const __half*)(Bbase + s * bStageBytes);

        #pragma unroll
        for (int ks = 0; ks < 2; ks++) {
            const int kb = ks * 16 + 2 * tig;
            uint32_t af[2][4];
            if (AH) {
                const __half* AsS = (const __half*)(Abase + s * aStageBytes);
                #pragma unroll
                for (int mt = 0; mt < 2; mt++) {
                    const int m0 = wm + mt * 16;
                    af[mt][0] = *(const uint32_t*)&AsS[(m0 + g) * FSTRH + kb];
                    af[mt][1] = *(const uint32_t*)&AsS[(m0 + g + 8) * FSTRH + kb];
                    af[mt][2] = *(const uint32_t*)&AsS[(m0 + g) * FSTRH + kb + 8];
                    af[mt][3] = *(const uint32_t*)&AsS[(m0 + g + 8) * FSTRH + kb + 8];
                }
            } else {
                const float* AsS = (const float*)(Abase + s * aStageBytes);
                #pragma unroll
                for (int mt = 0; mt < 2; mt++) {
                    const int m0 = wm + mt * 16;
                    float2 v0 = *(const float2*)&AsS[(m0 + g) * FSTRF + kb];
                    float2 v1 = *(const float2*)&AsS[(m0 + g + 8) * FSTRF + kb];
                    float2 v2 = *(const float2*)&AsS[(m0 + g) * FSTRF + kb + 8];
                    float2 v3 = *(const float2*)&AsS[(m0 + g + 8) * FSTRF + kb + 8];
                    af[mt][0] = packh2(v0.x, v0.y);
                    af[mt][1] = packh2(v1.x, v1.y);
                    af[mt][2] = packh2(v2.x, v2.y);
                    af[mt][3] = packh2(v3.x, v3.y);
                }
            }
            uint32_t bf[8][2];
            #pragma unroll
            for (int nt = 0; nt < 8; nt++) {
                const int n0 = wn + nt * 8;
                bf[nt][0] = *(const uint32_t*)&BsS[(n0 + g) * FSTRH + kb];
                bf[nt][1] = *(const uint32_t*)&BsS[(n0 + g) * FSTRH + kb + 8];
            }
            #pragma unroll
            for (int mt = 0; mt < 2; mt++)
                #pragma unroll
                for (int nt = 0; nt < 8; nt++)
                    mma16816(acc[mt][nt], af[mt][0], af[mt][1], af[mt][2], af[mt][3],
                             bf[nt][0], bf[nt][1]);
        }
        __syncthreads();
    }

    // epilogue
    #pragma unroll
    for (int mt = 0; mt < 2; mt++) {
        #pragma unroll
        for (int nt = 0; nt < 8; nt++) {
            const int c = colTile + wn + nt * 8 + tig * 2;
            const float b0 = bias[c], b1 = bias[c + 1];
            const int r0 = rowTile + wm + mt * 16 + g;
            if (CH) {
                __half* C = (__half*)Cv;
                *(__half2*)(C + (long)r0 * N + c) =
                    __floats2half2_rn(acc[mt][nt][0] + b0, acc[mt][nt][1] + b1);
                *(__half2*)(C + (long)(r0 + 8) * N + c) =
                    __floats2half2_rn(acc[mt][nt][2] + b0, acc[mt][nt][3] + b1);
            } else {
                float* C = (float*)Cv;
                *(float2*)(C + (long)r0 * N + c) =
                    make_float2(acc[mt][nt][0] + b0, acc[mt][nt][1] + b1);
                *(float2*)(C + (long)(r0 + 8) * N + c) =
                    make_float2(acc[mt][nt][2] + b0, acc[mt][nt][3] + b1);
            }
        }
    }
}

#define FP16_SMEM_F32A (FSTAGES * (FBM * FSTRF * 4 + FBN * FSTRH * 2))   // 85,248
#define FP16_SMEM_H16A (FSTAGES * (FBM * FSTRH * 2 + FBN * FSTRH * 2))   // 61,440

// ---------------------------------------------------------------------------
// mma.sync 3xTF32 split GEMM (precision-critical offset/attn projection only).
// ---------------------------------------------------------------------------
#define GBM 128
#define GBN 128
#define GBK 16
#define STAGES 4
#define AS_STRIDE 20
#define BS_STRIDE 132
#define GEMM_SMEM_BYTES (STAGES * (GBM * AS_STRIDE + GBK * BS_STRIDE) * 4)

__global__ __launch_bounds__(256) void tf32_split_gemm_kernel(
    const float* __restrict__ A, const float* __restrict__ B,
    const float* __restrict__ bias, float* __restrict__ C,
    int M, int N, int K)
{
    extern __shared__ __align__(16) float dsmf[];
    float* As = dsmf;
    float* Bs = dsmf + STAGES * GBM * AS_STRIDE;

    const int t = threadIdx.x;
    const int warp = t >> 5;
    const int lane = t & 31;
    const int g = lane >> 2;
    const int tig = lane & 3;
    const int wm = (warp >> 1) * 32;
    const int wn = (warp & 1) * 64;

    const int rowTile = blockIdx.y * GBM;
    const int colTile = blockIdx.x * GBN;

    const int ar0 = t >> 2;
    const int ar1 = ar0 + 64;
    const int ac = (t & 3) * 4;
    const int bk0 = t >> 5;
    const int bk1 = bk0 + 8;
    const int bc = (t & 31) * 4;

    const bool aok0 = (rowTile + ar0) < M;
    const bool aok1 = (rowTile + ar1) < M;
    const bool bok = (colTile + bc) < N;

    const float* Ap0 = A + (long)(rowTile + ar0) * K + ac;
    const float* Ap1 = A + (long)(rowTile + ar1) * K + ac;
    const float* Bp0 = B + (long)bk0 * N + colTile + bc;
    const float* Bp1 = B + (long)bk1 * N + colTile + bc;

    const uint32_t aStageB = GBM * AS_STRIDE * 4;
    const uint32_t bStageB = GBK * BS_STRIDE * 4;
    const uint32_t sA0 = (uint32_t)__cvta_generic_to_shared(As + ar0 * AS_STRIDE + ac);
    const uint32_t sA1 = (uint32_t)__cvta_generic_to_shared(As + ar1 * AS_STRIDE + ac);
    const uint32_t sB0 = (uint32_t)__cvta_generic_to_shared(Bs + bk0 * BS_STRIDE + bc);
    const uint32_t sB1 = (uint32_t)__cvta_generic_to_shared(Bs + bk1 * BS_STRIDE + bc);

    const int kIters = K / GBK;

    auto issue_tile = [&](int tile) {
        if (tile < kIters) {
            const int s = tile % STAGES;
            const long k0 = (long)tile * GBK;
            cpasync16p(sA0 + s * aStageB, Ap0 + k0, aok0);
            cpasync16p(sA1 + s * aStageB, Ap1 + k0, aok1);
            cpasync16p(sB0 + s * bStageB, Bp0 + k0 * N, bok);
            cpasync16p(sB1 + s * bStageB, Bp1 + k0 * N, bok);
        }
        cpasync_commit();
    };

    float acc[2][8][4];
    #pragma unroll
    for (int i = 0; i < 2; i++)
        #pragma unroll
        for (int j = 0; j < 8; j++)
            #pragma unroll
            for (int r = 0; r < 4; r++) acc[i][j][r] = 0.f;

    #pragma unroll
    for (int s = 0; s < STAGES - 1; s++) issue_tile(s);

    #pragma unroll 1
    for (int it = 0; it < kIters; ++it) {
        cpasync_wait<STAGES - 2>();
        __syncthreads();
        issue_tile(it + STAGES - 1);

        const int s = it % STAGES;
        const float* AsS = As + s * GBM * AS_STRIDE;
        const float* BsS = Bs + s * GBK * BS_STRIDE;

        #pragma unroll
        for (int kk = 0; kk < GBK; kk += 8) {
            float ar[2][4];
            #pragma unroll
            for (int mt = 0; mt < 2; mt++) {
                const int m0 = wm + mt * 16;
                ar[mt][0] = AsS[(m0 + g) * AS_STRIDE + kk + tig];
                ar[mt][1] = AsS[(m0 + g + 8) * AS_STRIDE + kk + tig];
                ar[mt][2] = AsS[(m0 + g) * AS_STRIDE + kk + tig + 4];
                ar[mt][3] = AsS[(m0 + g + 8) * AS_STRIDE + kk + tig + 4];
            }
            float br[8][2];
            #pragma unroll
            for (int nt = 0; nt < 8; nt++) {
                br[nt][0] = BsS[(kk + tig) * BS_STRIDE + wn + nt * 8 + g];
                br[nt][1] = BsS[(kk + tig + 4) * BS_STRIDE + wn + nt * 8 + g];
            }
            uint32_t ahi[2][4], alo[2][4];
            #pragma unroll
            for (int mt = 0; mt < 2; mt++)
                #pragma unroll
                for (int r = 0; r < 4; r++) {
                    float hi = tf32f(ar[mt][r]);
                    ahi[mt][r] = __float_as_uint(hi);
                    alo[mt][r] = f2tf32(ar[mt][r] - hi);
                }
            uint32_t bhi[8][2], blo[8][2];
            #pragma unroll
            for (int nt = 0; nt < 8; nt++)
                #pragma unroll
                for (int r = 0; r < 2; r++) {
                    float hi = tf32f(br[nt][r]);
                    bhi[nt][r] = __float_as_uint(hi);
                    blo[nt][r] = f2tf32(br[nt][r] - hi);
                }
            #pragma unroll
            for (int mt = 0; mt < 2; mt++)
                #pragma unroll
                for (int nt = 0; nt < 8; nt++) {
                    mma8(acc[mt][nt], ahi[mt][0], ahi[mt][1], ahi[mt][2], ahi[mt][3],
                         blo[nt][0], blo[nt][1]);
                    mma8(acc[mt][nt], alo[mt][0], alo[mt][1], alo[mt][2], alo[mt][3],
                         bhi[nt][0], bhi[nt][1]);
                    mma8(acc[mt][nt], ahi[mt][0], ahi[mt][1], ahi[mt][2], ahi[mt][3],
                         bhi[nt][0], bhi[nt][1]);
                }
        }
    }

    #pragma unroll
    for (int mt = 0; mt < 2; mt++) {
        #pragma unroll
        for (int nt = 0; nt < 8; nt++) {
            const int c = colTile + wn + nt * 8 + tig * 2;
            if (c >= N) continue;
            const float b0 = bias[c], b1 = bias[c + 1];
            const int r0 = rowTile + wm + mt * 16 + g;
            if (r0 < M) {
                float2 v = make_float2(acc[mt][nt][0] + b0, acc[mt][nt][1] + b1);
                *(float2*)(C + (long)r0 * N + c) = v;
            }
            const int r1 = r0 + 8;
            if (r1 < M) {
                float2 v = make_float2(acc[mt][nt][2] + b0, acc[mt][nt][3] + b1);
                *(float2*)(C + (long)r1 * N + c) = v;
            }
        }
    }
}

// ---------------------------------------------------------------------------
// Prep kernels
// ---------------------------------------------------------------------------
__global__ void prep_wcat_kernel(const float* __restrict__ W_off, const float* __restrict__ b_off,
                                 const float* __restrict__ W_attn, const float* __restrict__ b_attn)
{
    int i = blockIdx.x * blockDim.x + threadIdx.x;
    if (i < DMODEL * NPROJ) {
        int k = i / NPROJ, n = i % NPROJ;
        g_Wcat[i] = (n < 64) ? W_off[k * 64 + n] : W_attn[k * 32 + (n - 64)];
    }
    if (i < NPROJ) g_bcat[i] = (i < 64) ? b_off[i] : b_attn[i - 64];
}

// Transpose W_val / W_out (256x256) into half [N][K].
__global__ void transpose_w_kernel(const float* __restrict__ Wv, const float* __restrict__ Wo)
{
    __shared__ float t[32][33];
    const int which = blockIdx.x >> 6;
    const int bi = blockIdx.x & 63;
    const int tx = bi & 7, ty = bi >> 3;
    const float* W = which ? Wo : Wv;
    __half* T = which ? g_WoutTh : g_WvalTh;
    int x = tx * 32 + threadIdx.x;
    int y = ty * 32 + threadIdx.y;
    #pragma unroll
    for (int i = 0; i < 32; i += 8)
        t[threadIdx.y + i][threadIdx.x] = W[(y + i) * DMODEL + x];
    __syncthreads();
    x = ty * 32 + threadIdx.x;
    y = tx * 32 + threadIdx.y;
    #pragma unroll
    for (int i = 0; i < 32; i += 8)
        T[(y + i) * DMODEL + x] = __float2half_rn(t[threadIdx.x][threadIdx.y + i]);
}

// ---------------------------------------------------------------------------
// Prep table: coalesced smem staging of g_proj; thread = (bq_local, head).
// ---------------------------------------------------------------------------
__global__ __launch_bounds__(256) void prep_tab_kernel(
    const float* __restrict__ ref_pts,
    const int* __restrict__ hp, const int* __restrict__ wp)
{
    __shared__ float sproj[32 * NPROJ];
    __shared__ float sref[64];

    const int tid = threadIdx.x;
    const int bq0 = blockIdx.x * 32;

    #pragma unroll
    for (int j = 0; j < 12; j++)
        sproj[tid + j * 256] = g_proj[(long)bq0 * NPROJ + tid + j * 256];
    if (tid < 64) sref[tid] = ref_pts[(long)bq0 * 2 + tid];
    __syncthreads();

    const int bql = tid >> 3;
    const int h = tid & 7;
    const int bq = bq0 + bql;
    const int b = bq / QLEN;
    const float* pr = sproj + bql * NPROJ;

    float l0 = pr[64 + h * 4 + 0], l1 = pr[64 + h * 4 + 1];
    float l2 = pr[64 + h * 4 + 2], l3 = pr[64 + h * 4 + 3];
    float m = fmaxf(fmaxf(l0, l1), fmaxf(l2, l3));
    float e0 = expf(l0 - m), e1 = expf(l1 - m), e2 = expf(l2 - m), e3 = expf(l3 - m);
    float inv = 1.f / (e0 + e1 + e2 + e3);
    float attn[NPOINTS] = { e0 * inv, e1 * inv, e2 * inv, e3 * inv };

    const int ww = *wp;
    const int hh = *hp;
    const float rx = sref[bql * 2 + 0];
    const float ry = sref[bql * 2 + 1];
    const int vbase = b * HWTOT * DMODEL + h * DHEAD;

    const long tslot = (long)bq * NHEADS + h;
    int* ti = g_tidx + tslot * 16;
    float* tw = g_tw + tslot * 16;

    #pragma unroll
    for (int p = 0; p < NPOINTS; p++) {
        const int hp4 = h * NPOINTS + p;
        float lx = fminf(fmaxf(rx + pr[hp4 * 2 + 0], 0.f), 1.f);
        float ly = fminf(fmaxf(ry + pr[hp4 * 2 + 1], 0.f), 1.f);
        float sx = lx * (float)(ww - 1);
        float sy = ly * (float)(hh - 1);
        int x0 = (int)floorf(sx); x0 = min(max(x0, 0), ww - 1);
        int y0 = (int)floorf(sy); y0 = min(max(y0, 0), hh - 1);
        int x1 = min(x0 + 1, ww - 1);
        int y1 = min(y0 + 1, hh - 1);
        float wx1 = sx - (float)x0, wx0 = 1.f - wx1;
        float wy1 = sy - (float)y0, wy0 = 1.f - wy1;
        float a = attn[p];
        ti[p * 4 + 0] = vbase + (y0 * ww + x0) * DMODEL;
        ti[p * 4 + 1] = vbase + (y1 * ww + x0) * DMODEL;
        ti[p * 4 + 2] = vbase + (y0 * ww + x1) * DMODEL;
        ti[p * 4 + 3] = vbase + (y1 * ww + x1) * DMODEL;
        tw[p * 4 + 0] = wx0 * wy0 * a;
        tw[p * 4 + 1] = wx0 * wy1 * a;
        tw[p * 4 + 2] = wx1 * wy0 * a;
        tw[p * 4 + 3] = wx1 * wy1 * a;
    }
}

// ---------------------------------------------------------------------------
// Gather: warp = (bq, head), lane = channel; half values, half output.
// ---------------------------------------------------------------------------
__global__ __launch_bounds__(256) void gather_kernel()
{
    const int wg = (blockIdx.x * blockDim.x + threadIdx.x) >> 5;
    const int lane = threadIdx.x & 31;
    if (wg >= BATCH * QLEN * NHEADS) return;

    const int4* ti = (const int4*)(g_tidx + (long)wg * 16);
    const float4* tw = (const float4*)(g_tw + (long)wg * 16);

    float acc = 0.f;
    #pragma unroll
    for (int c = 0; c < 4; c++) {
        int4 id = ti[c];
        float4 w = tw[c];
        acc = fmaf(w.x, __half2float(g_valh[id.x + lane]), acc);
        acc = fmaf(w.y, __half2float(g_valh[id.y + lane]), acc);
        acc = fmaf(w.z, __half2float(g_valh[id.z + lane]), acc);
        acc = fmaf(w.w, __half2float(g_valh[id.w + lane]), acc);
    }

    const int bq = wg >> 3;
    const int h = wg & 7;
    g_samph[(long)bq * DMODEL + h * DHEAD + lane] = __float2half_rn(acc);
}

// ---------------------------------------------------------------------------
// Launch — two streams: s0 (value GEMM path) || s1 (proj path), join at gather.
// ---------------------------------------------------------------------------
extern "C" void kernel_launch(void* const* d_in, const int* in_sizes, int n_in,
                              void* d_out, int out_size)
{
    const float* query   = (const float*)d_in[0];
    const float* ref_pts = (const float*)d_in[1];
    const float* inp     = (const float*)d_in[2];
    const int*   hp      = (const int*)d_in[3];
    const int*   wp      = (const int*)d_in[4];
    const float* W_off   = (const float*)d_in[5];
    const float* b_off   = (const float*)d_in[6];
    const float* W_attn  = (const float*)d_in[7];
    const float* b_attn  = (const float*)d_in[8];
    const float* W_val   = (const float*)d_in[9];
    const float* b_val   = (const float*)d_in[10];
    const float* W_out   = (const float*)d_in[11];
    const float* b_out   = (const float*)d_in[12];
    float* out = (float*)d_out;

    __half *valh_ptr, *samph_ptr, *wvth_ptr, *woth_ptr;
    float *proj_ptr, *wcat_ptr, *bcat_ptr;
    cudaGetSymbolAddress((void**)&valh_ptr, g_valh);
    cudaGetSymbolAddress((void**)&samph_ptr, g_samph);
    cudaGetSymbolAddress((void**)&proj_ptr, g_proj);
    cudaGetSymbolAddress((void**)&wcat_ptr, g_Wcat);
    cudaGetSymbolAddress((void**)&bcat_ptr, g_bcat);
    cudaGetSymbolAddress((void**)&wvth_ptr, g_WvalTh);
    cudaGetSymbolAddress((void**)&woth_ptr, g_WoutTh);

    static cudaStream_t s1 = nullptr;
    static cudaEvent_t evFork = nullptr, evJoin = nullptr;
    if (!s1) {
        cudaStreamCreateWithFlags(&s1, cudaStreamNonBlocking);
        cudaEventCreateWithFlags(&evFork, cudaEventDisableTiming);
        cudaEventCreateWithFlags(&evJoin, cudaEventDisableTiming);
        cudaFuncSetAttribute(tf32_split_gemm_kernel,
                             cudaFuncAttributeMaxDynamicSharedMemorySize, GEMM_SMEM_BYTES);
        cudaFuncSetAttribute((fp16_gemm_kernel<false, true>),
                             cudaFuncAttributeMaxDynamicSharedMemorySize, FP16_SMEM_F32A);
        cudaFuncSetAttribute((fp16_gemm_kernel<true, false>),
                             cudaFuncAttributeMaxDynamicSharedMemorySize, FP16_SMEM_H16A);
    }

    const int M1 = BATCH * HWTOT;   // 80000
    const int MQ = BATCH * QLEN;    // 16384

    // ---- fork: s1 runs the (independent) projection path
    cudaEventRecord(evFork, 0);
    cudaStreamWaitEvent(s1, evFork, 0);

    prep_wcat_kernel<<<(DMODEL * NPROJ + 255) / 256, 256, 0, s1>>>(
        W_off, b_off, W_attn, b_attn);
    {
        dim3 grid(1, MQ / GBM);
        tf32_split_gemm_kernel<<<grid, 256, GEMM_SMEM_BYTES, s1>>>(
            query, wcat_ptr, bcat_ptr, proj_ptr, MQ, NPROJ, DMODEL);
    }
    prep_tab_kernel<<<MQ / 32, 256, 0, s1>>>(ref_pts, hp, wp);
    cudaEventRecord(evJoin, s1);

    // stream 0: transpose+halve weights, then the big value GEMM (fp32 A -> half C)
    transpose_w_kernel<<<128, dim3(32, 8)>>>(W_val, W_out);
    {
        dim3 grid(DMODEL / FBN, M1 / FBM);
        fp16_gemm_kernel<false, true><<<grid, 256, FP16_SMEM_F32A>>>(
            inp, wvth_ptr, b_val, valh_ptr, M1, DMODEL, DMODEL);
    }

    // ---- join: gather needs values (s0) + table (s1)
    cudaStreamWaitEvent(0, evJoin, 0);
    gather_kernel<<<(MQ * NHEADS) / 8, 256>>>();

    // out = sampled(h) @ W_out + b_out   (pure half GEMM, fp32 out)
    {
        dim3 grid(DMODEL / FBN, MQ / FBM);
        fp16_gemm_kernel<true, false><<<grid, 256, FP16_SMEM_H16A>>>(
            samph_ptr, woth_ptr, b_out, out, MQ, DMODEL, DMODEL);
    }
}